// round 1
// baseline (speedup 1.0000x reference)
#include <cuda_runtime.h>
#include <cstdint>

// Problem constants
#define B_   4
#define C_   256
#define H_   64
#define W_   64
#define HW_  4096            // H*W
#define KK_  9               // 3x3 taps
#define KD_  2304            // C*KK (GEMM K)
#define NP_  16384           // B*HW (GEMM N)
#define G_   32
#define EPS_ 1e-5f

// -------- scratch (device globals; no allocations allowed) --------
__device__ uint2  g_pos[B_ * KK_ * HW_];          // packed 4 corner positions (12-bit each, 2x16-bit per word)
__device__ float4 g_wt [B_ * KK_ * HW_];          // 4 bilinear weights (validity folded in)
__device__ float  g_xu [(size_t)KD_ * NP_];       // im2col matrix [2304 x 16384], ~151 MB
__device__ float  g_att[NP_];                     // attention accumulator -> sigmoid gate
__device__ float  g_mean[B_ * G_];
__device__ float  g_istd[B_ * G_];

// ================== kernel 0: sampling coords + weights ==================
// grid (16, 36) x 256 : blockIdx.y = b*9+kk, hw = blockIdx.x*256+tid
__global__ void k_coords(const float* __restrict__ off) {
    int bkk = blockIdx.y;
    int hw  = blockIdx.x * 256 + threadIdx.x;
    int b   = bkk / KK_;
    int kk  = bkk - b * KK_;
    int h   = hw >> 6;
    int w   = hw & 63;

    // zero the attention accumulator once per launch (graph-replay safe)
    if (bkk < 4) g_att[bkk * HW_ + hw] = 0.0f;

    float dy = off[(b * 18 + kk * 2    ) * HW_ + hw];
    float dx = off[(b * 18 + kk * 2 + 1) * HW_ + hw];

    float py = (float)h + (float)(kk / 3 - 1) + dy;
    float px = (float)w + (float)(kk % 3 - 1) + dx;

    float fy = floorf(py), fx = floorf(px);
    int iy0 = (int)fy, ix0 = (int)fx;
    float wy1 = py - fy, wy0 = 1.0f - wy1;
    float wx1 = px - fx, wx0 = 1.0f - wx1;

    bool vy0 = (iy0 >= 0)  && (iy0 < H_);
    bool vy1 = (iy0 >= -1) && (iy0 < H_ - 1);
    bool vx0 = (ix0 >= 0)  && (ix0 < W_);
    bool vx1 = (ix0 >= -1) && (ix0 < W_ - 1);

    float4 wt;
    wt.x = wy0 * wx0 * (float)(vy0 && vx0);
    wt.y = wy0 * wx1 * (float)(vy0 && vx1);
    wt.z = wy1 * wx0 * (float)(vy1 && vx0);
    wt.w = wy1 * wx1 * (float)(vy1 && vx1);

    int y0c = min(max(iy0, 0), H_ - 1);
    int y1c = min(max(iy0 + 1, 0), H_ - 1);
    int x0c = min(max(ix0, 0), W_ - 1);
    int x1c = min(max(ix0 + 1, 0), W_ - 1);

    unsigned p00 = (unsigned)(y0c * W_ + x0c);
    unsigned p01 = (unsigned)(y0c * W_ + x1c);
    unsigned p10 = (unsigned)(y1c * W_ + x0c);
    unsigned p11 = (unsigned)(y1c * W_ + x1c);

    int ci = bkk * HW_ + hw;
    g_pos[ci] = make_uint2(p00 | (p01 << 16), p10 | (p11 << 16));
    g_wt[ci]  = wt;
}

// ================== kernel 1: im2col (bilinear deformable unfold) ==================
// grid (64, 2304) x 256 : blockIdx.y = row = c*9+kk; p = blockIdx.x*256+tid
__global__ void k_im2col(const float* __restrict__ x) {
    int row = blockIdx.y;
    int p   = blockIdx.x * 256 + threadIdx.x;
    int c   = row / KK_;
    int kk  = row - c * KK_;
    int b   = p >> 12;
    int hw  = p & 4095;

    int ci = (b * KK_ + kk) * HW_ + hw;
    uint2  pos = g_pos[ci];
    float4 wt  = g_wt[ci];

    const float* xb = x + ((size_t)(b * C_ + c)) * HW_;
    float v = wt.x * xb[pos.x & 0xFFFFu]
            + wt.y * xb[pos.x >> 16]
            + wt.z * xb[pos.y & 0xFFFFu]
            + wt.w * xb[pos.y >> 16];

    g_xu[(size_t)row * NP_ + p] = v;
}

// ================== kernel 2: attention partial reduction ==================
// grid (64, 8) x 256 : 32 channels per block.y, atomic partial sums
__global__ void k_attpart(const float* __restrict__ attw) {
    int p  = blockIdx.x * 256 + threadIdx.x;
    int c0 = blockIdx.y * 32;
    float acc = 0.0f;
    for (int c = c0; c < c0 + 32; ++c) {
        const float* col = g_xu + (size_t)(c * KK_) * NP_ + p;
        float m = col[0];
        #pragma unroll
        for (int kk = 1; kk < KK_; ++kk)
            m = fmaxf(m, col[(size_t)kk * NP_]);
        acc += attw[c] * m;
    }
    atomicAdd(&g_att[p], acc);
}

// ================== kernel 2b: sigmoid ==================
__global__ void k_sigmoid(const float* __restrict__ attb) {
    int p = blockIdx.x * 256 + threadIdx.x;
    float v = g_att[p] + attb[0];
    g_att[p] = 1.0f / (1.0f + expf(-v));
}

// ================== kernel 3: GEMM  out[o,p] = sum_k W[o,k]*xu[k,p], epilogue * att ==================
// BM=128, BN=128, BK=16, 256 threads, 8x8 per thread
__global__ __launch_bounds__(256) void k_gemm(const float* __restrict__ A, float* __restrict__ out) {
    __shared__ float As[16][128];
    __shared__ float Bs[16][128];

    int tid  = threadIdx.x;
    int row0 = blockIdx.y * 128;
    int col0 = blockIdx.x * 128;

    float acc[8][8] = {};

    const float* Ab = A + (size_t)row0 * KD_;

    for (int k0 = 0; k0 < KD_; k0 += 16) {
        // load A tile 128x16, transpose into As[k][m]
        #pragma unroll
        for (int it = 0; it < 2; ++it) {
            int ar = (tid >> 2) + it * 64;
            int ac = (tid & 3) * 4;
            float4 av = *(const float4*)(Ab + (size_t)ar * KD_ + k0 + ac);
            As[ac + 0][ar] = av.x;
            As[ac + 1][ar] = av.y;
            As[ac + 2][ar] = av.z;
            As[ac + 3][ar] = av.w;
        }
        // load B tile 16x128 direct
        #pragma unroll
        for (int it = 0; it < 2; ++it) {
            int br = (tid >> 5) + it * 8;
            int bc = (tid & 31) * 4;
            *(float4*)&Bs[br][bc] = *(const float4*)(g_xu + (size_t)(k0 + br) * NP_ + col0 + bc);
        }
        __syncthreads();

        int ty = tid >> 4, tx = tid & 15;
        #pragma unroll
        for (int kk = 0; kk < 16; ++kk) {
            float a[8], bb[8];
            *(float4*)(a)     = *(const float4*)&As[kk][ty * 8];
            *(float4*)(a + 4) = *(const float4*)&As[kk][ty * 8 + 4];
            *(float4*)(bb)     = *(const float4*)&Bs[kk][tx * 8];
            *(float4*)(bb + 4) = *(const float4*)&Bs[kk][tx * 8 + 4];
            #pragma unroll
            for (int i = 0; i < 8; ++i)
                #pragma unroll
                for (int j = 0; j < 8; ++j)
                    acc[i][j] += a[i] * bb[j];
        }
        __syncthreads();
    }

    // epilogue: multiply by att, scatter into d_out laid out [b, o, hw]
    int ty = tid >> 4, tx = tid & 15;
    int p0 = col0 + tx * 8;
    int b  = p0 >> 12;
    int hw0 = p0 & 4095;

    float attv[8];
    #pragma unroll
    for (int j = 0; j < 8; ++j) attv[j] = g_att[p0 + j];

    #pragma unroll
    for (int i = 0; i < 8; ++i) {
        int o = row0 + ty * 8 + i;
        float* orow = out + ((size_t)(b * C_ + o)) * HW_ + hw0;
        float4 v0, v1;
        v0.x = acc[i][0] * attv[0]; v0.y = acc[i][1] * attv[1];
        v0.z = acc[i][2] * attv[2]; v0.w = acc[i][3] * attv[3];
        v1.x = acc[i][4] * attv[4]; v1.y = acc[i][5] * attv[5];
        v1.z = acc[i][6] * attv[6]; v1.w = acc[i][7] * attv[7];
        *(float4*)(orow)     = v0;
        *(float4*)(orow + 4) = v1;
    }
}

// ================== kernel 4: GroupNorm stats ==================
// grid 128 (one block per (b,g)), 256 threads; reduces 8*4096 elements
__global__ void k_stats(const float* __restrict__ out) {
    int bg = blockIdx.x;
    const float* base = out + (size_t)bg * (8 * HW_);
    float s = 0.0f, s2 = 0.0f;
    for (int i = threadIdx.x; i < 8 * HW_; i += 256) {
        float v = base[i];
        s += v; s2 += v * v;
    }
    __shared__ float ss[256], ss2[256];
    ss[threadIdx.x] = s; ss2[threadIdx.x] = s2;
    __syncthreads();
    for (int st = 128; st > 0; st >>= 1) {
        if (threadIdx.x < st) {
            ss[threadIdx.x]  += ss[threadIdx.x + st];
            ss2[threadIdx.x] += ss2[threadIdx.x + st];
        }
        __syncthreads();
    }
    if (threadIdx.x == 0) {
        float inv_n = 1.0f / (8.0f * HW_);
        float mean = ss[0] * inv_n;
        float var  = ss2[0] * inv_n - mean * mean;
        g_mean[bg] = mean;
        g_istd[bg] = rsqrtf(var + EPS_);
    }
}

// ================== kernel 5: normalize + affine + ReLU (in place) ==================
__global__ void k_norm(float* __restrict__ out,
                       const float* __restrict__ gamma,
                       const float* __restrict__ beta) {
    int idx = blockIdx.x * 256 + threadIdx.x;      // < 4*256*4096
    float v = out[idx];
    int c  = (idx >> 12) & 255;
    int bg = idx >> 15;                            // (b*256+c)/8 = b*32 + c/8
    v = (v - g_mean[bg]) * g_istd[bg] * gamma[c] + beta[c];
    out[idx] = fmaxf(v, 0.0f);
}

// ================== launch ==================
extern "C" void kernel_launch(void* const* d_in, const int* in_sizes, int n_in,
                              void* d_out, int out_size) {
    const float* x     = (const float*)d_in[0];
    const float* off   = (const float*)d_in[1];
    const float* wgt   = (const float*)d_in[2];
    const float* attw  = (const float*)d_in[3];
    const float* attb  = (const float*)d_in[4];
    const float* gamma = (const float*)d_in[5];
    const float* beta  = (const float*)d_in[6];
    float* out = (float*)d_out;

    k_coords  <<<dim3(16, B_ * KK_), 256>>>(off);
    k_im2col  <<<dim3(NP_ / 256, KD_), 256>>>(x);
    k_attpart <<<dim3(NP_ / 256, 8), 256>>>(attw);
    k_sigmoid <<<NP_ / 256, 256>>>(attb);
    k_gemm    <<<dim3(NP_ / 128, C_ / 128), 256>>>(wgt, out);
    k_stats   <<<B_ * G_, 256>>>(out);
    k_norm    <<<(B_ * C_ * HW_) / 256, 256>>>(out, gamma, beta);
}

// round 3
// speedup vs baseline: 1.4579x; 1.4579x over previous
#include <cuda_runtime.h>
#include <cuda_bf16.h>
#include <cstdint>

// Problem constants
#define B_   4
#define C_   256
#define H_   64
#define W_   64
#define HW_  4096
#define KK_  9
#define KD_  2304            // C*KK (GEMM K), reordered as k = kk*256 + c
#define NP_  16384           // B*HW (GEMM N)
#define G_   32
#define EPS_ 1e-5f

// ---------------- helpers ----------------
__device__ __forceinline__ uint32_t smem_to_u32(const void* p) {
    uint32_t a;
    asm("{ .reg .u64 t; cvta.to.shared.u64 t, %1; cvt.u32.u64 %0, t; }" : "=r"(a) : "l"(p));
    return a;
}
__device__ __forceinline__ void cp16(uint32_t saddr, const void* g) {
    asm volatile("cp.async.cg.shared.global [%0], [%1], 16;" :: "r"(saddr), "l"(g));
}
#define CP_COMMIT() asm volatile("cp.async.commit_group;" ::: "memory")
#define CP_WAIT(n)  asm volatile("cp.async.wait_group %0;" :: "n"(n) : "memory")

__device__ __forceinline__ void ldsm_x4(uint32_t* r, uint32_t addr) {
    asm volatile("ldmatrix.sync.aligned.m8n8.x4.shared.b16 {%0,%1,%2,%3}, [%4];"
                 : "=r"(r[0]), "=r"(r[1]), "=r"(r[2]), "=r"(r[3]) : "r"(addr));
}
__device__ __forceinline__ void mma_bf16(float* d, const uint32_t* a, uint32_t b0, uint32_t b1) {
    asm volatile(
        "mma.sync.aligned.m16n8k16.row.col.f32.bf16.bf16.f32 "
        "{%0,%1,%2,%3}, {%4,%5,%6,%7}, {%8,%9}, {%0,%1,%2,%3};"
        : "+f"(d[0]), "+f"(d[1]), "+f"(d[2]), "+f"(d[3])
        : "r"(a[0]), "r"(a[1]), "r"(a[2]), "r"(a[3]), "r"(b0), "r"(b1));
}

// -------- scratch (device globals) --------
__device__ uint2          g_pos[B_ * KK_ * HW_];
__device__ float4         g_wt [B_ * KK_ * HW_];
__device__ __nv_bfloat16  g_ahi[C_ * KD_];            // weights hi [o][kk*256+c]
__device__ __nv_bfloat16  g_alo[C_ * KD_];
__device__ __nv_bfloat16  g_bhi[(size_t)NP_ * KD_];   // im2col hi [p][kk*256+c]
__device__ __nv_bfloat16  g_blo[(size_t)NP_ * KD_];
__device__ float          g_att[NP_];
__device__ float          g_mean[B_ * G_];
__device__ float          g_istd[B_ * G_];

// ================== kernel 0: sampling coords + weights ==================
__global__ void k_coords(const float* __restrict__ off) {
    int bkk = blockIdx.y;
    int hw  = blockIdx.x * 256 + threadIdx.x;
    int b   = bkk / KK_;
    int kk  = bkk - b * KK_;
    int h   = hw >> 6;
    int w   = hw & 63;

    float dy = off[(b * 18 + kk * 2    ) * HW_ + hw];
    float dx = off[(b * 18 + kk * 2 + 1) * HW_ + hw];

    float py = (float)h + (float)(kk / 3 - 1) + dy;
    float px = (float)w + (float)(kk % 3 - 1) + dx;

    float fy = floorf(py), fx = floorf(px);
    int iy0 = (int)fy, ix0 = (int)fx;
    float wy1 = py - fy, wy0 = 1.0f - wy1;
    float wx1 = px - fx, wx0 = 1.0f - wx1;

    bool vy0 = (iy0 >= 0)  && (iy0 < H_);
    bool vy1 = (iy0 >= -1) && (iy0 < H_ - 1);
    bool vx0 = (ix0 >= 0)  && (ix0 < W_);
    bool vx1 = (ix0 >= -1) && (ix0 < W_ - 1);

    float4 wt;
    wt.x = wy0 * wx0 * (float)(vy0 && vx0);
    wt.y = wy0 * wx1 * (float)(vy0 && vx1);
    wt.z = wy1 * wx0 * (float)(vy1 && vx0);
    wt.w = wy1 * wx1 * (float)(vy1 && vx1);

    int y0c = min(max(iy0, 0), H_ - 1);
    int y1c = min(max(iy0 + 1, 0), H_ - 1);
    int x0c = min(max(ix0, 0), W_ - 1);
    int x1c = min(max(ix0 + 1, 0), W_ - 1);

    unsigned p00 = (unsigned)(y0c * W_ + x0c);
    unsigned p01 = (unsigned)(y0c * W_ + x1c);
    unsigned p10 = (unsigned)(y1c * W_ + x0c);
    unsigned p11 = (unsigned)(y1c * W_ + x1c);

    int ci = bkk * HW_ + hw;
    g_pos[ci] = make_uint2(p00 | (p01 << 16), p10 | (p11 << 16));
    g_wt[ci]  = wt;
}

// ================== kernel 1: weight split to bf16 hi/lo, reordered k ==================
__global__ void k_wsplit(const float* __restrict__ wgt) {
    int idx = blockIdx.x * 256 + threadIdx.x;   // o*2304 + kk*256 + c
    int o = idx / KD_;
    int k = idx - o * KD_;
    int kk = k >> 8;
    int c  = k & 255;
    float v = wgt[(o * 256 + c) * 9 + kk];
    __nv_bfloat16 h = __float2bfloat16(v);
    g_ahi[idx] = h;
    g_alo[idx] = __float2bfloat16(v - __bfloat162float(h));
}

// ================== kernel 2: im2col -> bf16 hi/lo in [p][kk*256+c] ==================
// grid (128 hw-tiles of 32, 36 = b*kk), block 256
__global__ void k_im2col(const float* __restrict__ x) {
    __shared__ float stage[32][257];
    __shared__ uint2 spos[32];
    __shared__ float4 swt[32];

    int bkk = blockIdx.y;
    int b = bkk / KK_;
    int kk = bkk - b * KK_;
    int hw0 = blockIdx.x * 32;
    int tid = threadIdx.x, lane = tid & 31, w = tid >> 5;

    if (tid < 32) {
        spos[tid] = g_pos[bkk * HW_ + hw0 + tid];
        swt[tid]  = g_wt [bkk * HW_ + hw0 + tid];
    }
    __syncthreads();

    uint2 pos = spos[lane];
    float4 wt = swt[lane];
    const float* xb0 = x + (size_t)b * C_ * HW_;

    #pragma unroll 4
    for (int c = w; c < C_; c += 8) {
        const float* xb = xb0 + c * HW_;
        float v = wt.x * xb[pos.x & 0xFFFFu]
                + wt.y * xb[pos.x >> 16]
                + wt.z * xb[pos.y & 0xFFFFu]
                + wt.w * xb[pos.y >> 16];
        stage[lane][c] = v;
    }
    __syncthreads();

    int pl = tid >> 3;
    int c0 = (tid & 7) * 32;
    int p  = b * HW_ + hw0 + pl;
    size_t base = (size_t)p * KD_ + kk * 256 + c0;

    union { __nv_bfloat16 bb[32]; uint4 v[4]; } uh, ul;
    #pragma unroll
    for (int j = 0; j < 32; ++j) {
        float v = stage[pl][c0 + j];
        __nv_bfloat16 h = __float2bfloat16(v);
        uh.bb[j] = h;
        ul.bb[j] = __float2bfloat16(v - __bfloat162float(h));
    }
    uint4* dh = (uint4*)(g_bhi + base);
    uint4* dl = (uint4*)(g_blo + base);
    #pragma unroll
    for (int j = 0; j < 4; ++j) { dh[j] = uh.v[j]; dl[j] = ul.v[j]; }
}

// ================== kernel 3: attention (max over taps, dot, sigmoid) ==================
__global__ void k_att(const float* __restrict__ attw, const float* __restrict__ attb) {
    int tid = threadIdx.x, lane = tid & 31;
    int p = blockIdx.x * 8 + (tid >> 5);

    const uint4* bh = (const uint4*)(g_bhi + (size_t)p * KD_);
    const uint4* bl = (const uint4*)(g_blo + (size_t)p * KD_);

    float mx[8];
    #pragma unroll
    for (int j = 0; j < 8; ++j) mx[j] = -1e30f;

    #pragma unroll
    for (int kk = 0; kk < KK_; ++kk) {
        uint4 hv = bh[kk * 32 + lane];
        uint4 lv = bl[kk * 32 + lane];
        const __nv_bfloat16* hp = (const __nv_bfloat16*)&hv;
        const __nv_bfloat16* lp = (const __nv_bfloat16*)&lv;
        #pragma unroll
        for (int j = 0; j < 8; ++j) {
            float v = __bfloat162float(hp[j]) + __bfloat162float(lp[j]);
            mx[j] = fmaxf(mx[j], v);
        }
    }
    int c0 = lane * 8;
    float acc = 0.0f;
    #pragma unroll
    for (int j = 0; j < 8; ++j) acc += attw[c0 + j] * mx[j];
    #pragma unroll
    for (int s = 16; s; s >>= 1) acc += __shfl_xor_sync(0xFFFFFFFFu, acc, s);
    if (lane == 0) g_att[p] = 1.0f / (1.0f + __expf(-(acc + attb[0])));
}

// ================== kernel 4: mma.sync split-bf16 GEMM + att epilogue ==================
// CTA 128(M)x256(N), K-tile 32, 512 threads (16 warps, warp tile 32x64),
// double-buffered cp.async, smem rows padded to 80B for conflict-free ldmatrix.
// Stage layout: Ahi[128x40] Alo[128x40] Bhi[256x40] Blo[256x40] bf16 (61440 B).
#define ST_A_HI 0
#define ST_A_LO 10240
#define ST_B_HI 20480
#define ST_B_LO 40960
#define STAGE_B 61440
#define GEMM_SMEM (2 * STAGE_B)

__device__ __forceinline__ void load_stage(uint32_t sm, int kt, int m0, int p0, int tid) {
    int k0 = kt * 32;
    {
        int r = tid >> 2, q = tid & 3;  // 128 rows x 4 chunks
        size_t goff = (size_t)(m0 + r) * KD_ + k0 + q * 8;
        cp16(sm + ST_A_HI + r * 80 + q * 16, g_ahi + goff);
        cp16(sm + ST_A_LO + r * 80 + q * 16, g_alo + goff);
    }
    #pragma unroll
    for (int i = 0; i < 2; ++i) {
        int idx = tid + i * 512;        // 256 rows x 4 chunks
        int r = idx >> 2, q = idx & 3;
        size_t goff = (size_t)(p0 + r) * KD_ + k0 + q * 8;
        cp16(sm + ST_B_HI + r * 80 + q * 16, g_bhi + goff);
        cp16(sm + ST_B_LO + r * 80 + q * 16, g_blo + goff);
    }
}

// ldmatrix.x4 address: 16 rows (lanes 0-15), two 16B k-halves (lanes 16-31)
__device__ __forceinline__ uint32_t ldsm_addr(uint32_t base, int lane, int row0, int kb0) {
    return base + (uint32_t)(row0 + (lane & 15)) * 80u + (uint32_t)(kb0 + ((lane >> 4) << 4));
}

__global__ __launch_bounds__(512, 1) void k_gemm(float* __restrict__ out) {
    extern __shared__ __align__(128) char smem[];
    uint32_t sbase = smem_to_u32(smem);
    int tid = threadIdx.x, wid = tid >> 5, lane = tid & 31;
    int warpM = wid >> 2, warpN = wid & 3;
    int p0 = blockIdx.x * 256;
    int m0 = blockIdx.y * 128;

    float acc[2][8][4];
    #pragma unroll
    for (int i = 0; i < 2; ++i)
        #pragma unroll
        for (int j = 0; j < 8; ++j)
            #pragma unroll
            for (int q = 0; q < 4; ++q) acc[i][j][q] = 0.0f;

    load_stage(sbase, 0, m0, p0, tid);
    CP_COMMIT();

    for (int kt = 0; kt < 72; ++kt) {
        uint32_t cur = sbase + (uint32_t)(kt & 1) * STAGE_B;
        if (kt + 1 < 72) {
            load_stage(sbase + (uint32_t)((kt + 1) & 1) * STAGE_B, kt + 1, m0, p0, tid);
            CP_COMMIT();
            CP_WAIT(1);
        } else {
            CP_WAIT(0);
        }
        __syncthreads();

        #pragma unroll
        for (int ks = 0; ks < 2; ++ks) {
            uint32_t ah[2][4], al[2][4];
            #pragma unroll
            for (int mt = 0; mt < 2; ++mt) {
                int row = warpM * 32 + mt * 16;
                ldsm_x4(ah[mt], ldsm_addr(cur + ST_A_HI, lane, row, ks * 32));
                ldsm_x4(al[mt], ldsm_addr(cur + ST_A_LO, lane, row, ks * 32));
            }
            #pragma unroll
            for (int ntp = 0; ntp < 4; ++ntp) {
                int nrow = warpN * 64 + ntp * 16;
                uint32_t bh[4], bl[4];
                ldsm_x4(bh, ldsm_addr(cur + ST_B_HI, lane, nrow, ks * 32));
                ldsm_x4(bl, ldsm_addr(cur + ST_B_LO, lane, nrow, ks * 32));
                #pragma unroll
                for (int mt = 0; mt < 2; ++mt) {
                    mma_bf16(acc[mt][ntp * 2],     ah[mt], bh[0], bh[2]);
                    mma_bf16(acc[mt][ntp * 2],     ah[mt], bl[0], bl[2]);
                    mma_bf16(acc[mt][ntp * 2],     al[mt], bh[0], bh[2]);
                    mma_bf16(acc[mt][ntp * 2 + 1], ah[mt], bh[1], bh[3]);
                    mma_bf16(acc[mt][ntp * 2 + 1], ah[mt], bl[1], bl[3]);
                    mma_bf16(acc[mt][ntp * 2 + 1], al[mt], bh[1], bh[3]);
                }
            }
        }
        __syncthreads();
    }

    // epilogue: multiply by att, write f32 to out[b][o][hw]
    int b   = p0 >> 12;
    int hw0 = p0 & 4095;
    int qrow = lane >> 2, qcol = (lane & 3) * 2;

    #pragma unroll
    for (int nt = 0; nt < 8; ++nt) {
        int n = warpN * 64 + nt * 8 + qcol;
        float2 av = *(const float2*)&g_att[p0 + n];
        #pragma unroll
        for (int mt = 0; mt < 2; ++mt) {
            int o = m0 + warpM * 32 + mt * 16 + qrow;
            float* base0 = out + ((size_t)(b * C_ + o)) * HW_ + hw0 + n;
            float* base1 = base0 + 8 * HW_;
            float2 v0, v1;
            v0.x = acc[mt][nt][0] * av.x;  v0.y = acc[mt][nt][1] * av.y;
            v1.x = acc[mt][nt][2] * av.x;  v1.y = acc[mt][nt][3] * av.y;
            *(float2*)base0 = v0;
            *(float2*)base1 = v1;
        }
    }
}

// ================== kernel 5: GroupNorm stats ==================
__global__ void k_stats(const float* __restrict__ out) {
    int bg = blockIdx.x;
    const float* base = out + (size_t)bg * (8 * HW_);
    float s = 0.0f, s2 = 0.0f;
    for (int i = threadIdx.x; i < 8 * HW_; i += 256) {
        float v = base[i];
        s += v; s2 += v * v;
    }
    __shared__ float ss[256], ss2[256];
    ss[threadIdx.x] = s; ss2[threadIdx.x] = s2;
    __syncthreads();
    for (int st = 128; st > 0; st >>= 1) {
        if (threadIdx.x < st) {
            ss[threadIdx.x]  += ss[threadIdx.x + st];
            ss2[threadIdx.x] += ss2[threadIdx.x + st];
        }
        __syncthreads();
    }
    if (threadIdx.x == 0) {
        float inv_n = 1.0f / (8.0f * HW_);
        float mean = ss[0] * inv_n;
        float var  = ss2[0] * inv_n - mean * mean;
        g_mean[bg] = mean;
        g_istd[bg] = rsqrtf(var + EPS_);
    }
}

// ================== kernel 6: normalize + affine + ReLU ==================
__global__ void k_norm(float* __restrict__ out,
                       const float* __restrict__ gamma,
                       const float* __restrict__ beta) {
    int idx = blockIdx.x * 256 + threadIdx.x;
    float v = out[idx];
    int c  = (idx >> 12) & 255;
    int bg = idx >> 15;
    v = (v - g_mean[bg]) * g_istd[bg] * gamma[c] + beta[c];
    out[idx] = fmaxf(v, 0.0f);
}

// ================== launch ==================
extern "C" void kernel_launch(void* const* d_in, const int* in_sizes, int n_in,
                              void* d_out, int out_size) {
    const float* x     = (const float*)d_in[0];
    const float* off   = (const float*)d_in[1];
    const float* wgt   = (const float*)d_in[2];
    const float* attw  = (const float*)d_in[3];
    const float* attb  = (const float*)d_in[4];
    const float* gamma = (const float*)d_in[5];
    const float* beta  = (const float*)d_in[6];
    float* out = (float*)d_out;

    static bool configured = false;
    if (!configured) {
        cudaFuncSetAttribute(k_gemm, cudaFuncAttributeMaxDynamicSharedMemorySize, GEMM_SMEM);
        configured = true;
    }

    k_coords <<<dim3(16, B_ * KK_), 256>>>(off);
    k_wsplit <<<(C_ * KD_) / 256, 256>>>(wgt);
    k_im2col <<<dim3(HW_ / 32, B_ * KK_), 256>>>(x);
    k_att    <<<NP_ / 8, 256>>>(attw, attb);
    k_gemm   <<<dim3(NP_ / 256, C_ / 128), 512, GEMM_SMEM>>>(out);
    k_stats  <<<B_ * G_, 256>>>(out);
    k_norm   <<<(B_ * C_ * HW_) / 256, 256>>>(out, gamma, beta);
}

// round 4
// speedup vs baseline: 1.6809x; 1.1529x over previous
#include <cuda_runtime.h>
#include <cuda_bf16.h>
#include <cstdint>

// Problem constants
#define B_   4
#define C_   256
#define H_   64
#define W_   64
#define HW_  4096
#define KK_  9
#define KD_  2304            // C*KK (GEMM K), reordered as k = kk*256 + c
#define NP_  16384           // B*HW (GEMM N)
#define G_   32
#define EPS_ 1e-5f

// ---------------- helpers ----------------
__device__ __forceinline__ uint32_t smem_to_u32(const void* p) {
    uint32_t a;
    asm("{ .reg .u64 t; cvta.to.shared.u64 t, %1; cvt.u32.u64 %0, t; }" : "=r"(a) : "l"(p));
    return a;
}
__device__ __forceinline__ void cp16(uint32_t saddr, const void* g) {
    asm volatile("cp.async.cg.shared.global [%0], [%1], 16;" :: "r"(saddr), "l"(g));
}
#define CP_COMMIT() asm volatile("cp.async.commit_group;" ::: "memory")
#define CP_WAIT(n)  asm volatile("cp.async.wait_group %0;" :: "n"(n) : "memory")

__device__ __forceinline__ void ldsm_x4(uint32_t* r, uint32_t addr) {
    asm volatile("ldmatrix.sync.aligned.m8n8.x4.shared.b16 {%0,%1,%2,%3}, [%4];"
                 : "=r"(r[0]), "=r"(r[1]), "=r"(r[2]), "=r"(r[3]) : "r"(addr));
}
__device__ __forceinline__ void mma_bf16(float* d, const uint32_t* a, uint32_t b0, uint32_t b1) {
    asm volatile(
        "mma.sync.aligned.m16n8k16.row.col.f32.bf16.bf16.f32 "
        "{%0,%1,%2,%3}, {%4,%5,%6,%7}, {%8,%9}, {%0,%1,%2,%3};"
        : "+f"(d[0]), "+f"(d[1]), "+f"(d[2]), "+f"(d[3])
        : "r"(a[0]), "r"(a[1]), "r"(a[2]), "r"(a[3]), "r"(b0), "r"(b1));
}

// -------- scratch (device globals) --------
__device__ uint2          g_pos[B_ * KK_ * HW_];
__device__ float4         g_wt [B_ * KK_ * HW_];
__device__ __nv_bfloat16  g_ahi[C_ * KD_];            // weights hi [o][kk*256+c]
__device__ __nv_bfloat16  g_alo[C_ * KD_];
__device__ __nv_bfloat16  g_bhi[(size_t)NP_ * KD_];   // im2col hi [p][kk*256+c]
__device__ __nv_bfloat16  g_blo[(size_t)NP_ * KD_];
__device__ float          g_att[NP_];
__device__ float          g_gsum [B_ * G_];
__device__ float          g_gsum2[B_ * G_];
__device__ float          g_mean[B_ * G_];
__device__ float          g_istd[B_ * G_];

// ================== kernel 0: sampling coords + weights (+ zero group sums) ==================
__global__ void k_coords(const float* __restrict__ off) {
    int bkk = blockIdx.y;
    int hw  = blockIdx.x * 256 + threadIdx.x;
    int b   = bkk / KK_;
    int kk  = bkk - b * KK_;
    int h   = hw >> 6;
    int w   = hw & 63;

    if (blockIdx.x == 0 && blockIdx.y == 0) {
        int t = threadIdx.x;
        if (t < 128)      g_gsum [t] = 0.0f;
        else              g_gsum2[t - 128] = 0.0f;
    }

    float dy = off[(b * 18 + kk * 2    ) * HW_ + hw];
    float dx = off[(b * 18 + kk * 2 + 1) * HW_ + hw];

    float py = (float)h + (float)(kk / 3 - 1) + dy;
    float px = (float)w + (float)(kk % 3 - 1) + dx;

    float fy = floorf(py), fx = floorf(px);
    int iy0 = (int)fy, ix0 = (int)fx;
    float wy1 = py - fy, wy0 = 1.0f - wy1;
    float wx1 = px - fx, wx0 = 1.0f - wx1;

    bool vy0 = (iy0 >= 0)  && (iy0 < H_);
    bool vy1 = (iy0 >= -1) && (iy0 < H_ - 1);
    bool vx0 = (ix0 >= 0)  && (ix0 < W_);
    bool vx1 = (ix0 >= -1) && (ix0 < W_ - 1);

    float4 wt;
    wt.x = wy0 * wx0 * (float)(vy0 && vx0);
    wt.y = wy0 * wx1 * (float)(vy0 && vx1);
    wt.z = wy1 * wx0 * (float)(vy1 && vx0);
    wt.w = wy1 * wx1 * (float)(vy1 && vx1);

    int y0c = min(max(iy0, 0), H_ - 1);
    int y1c = min(max(iy0 + 1, 0), H_ - 1);
    int x0c = min(max(ix0, 0), W_ - 1);
    int x1c = min(max(ix0 + 1, 0), W_ - 1);

    unsigned p00 = (unsigned)(y0c * W_ + x0c);
    unsigned p01 = (unsigned)(y0c * W_ + x1c);
    unsigned p10 = (unsigned)(y1c * W_ + x0c);
    unsigned p11 = (unsigned)(y1c * W_ + x1c);

    int ci = bkk * HW_ + hw;
    g_pos[ci] = make_uint2(p00 | (p01 << 16), p10 | (p11 << 16));
    g_wt[ci]  = wt;
}

// ================== kernel 1: weight split to bf16 hi/lo, reordered k ==================
__global__ void k_wsplit(const float* __restrict__ wgt) {
    int idx = blockIdx.x * 256 + threadIdx.x;   // o*2304 + kk*256 + c
    int o = idx / KD_;
    int k = idx - o * KD_;
    int kk = k >> 8;
    int c  = k & 255;
    float v = wgt[(o * 256 + c) * 9 + kk];
    __nv_bfloat16 h = __float2bfloat16(v);
    g_ahi[idx] = h;
    g_alo[idx] = __float2bfloat16(v - __bfloat162float(h));
}

// ================== kernel 2: im2col + fused attention ==================
// grid (128 hw-tiles of 32, 4 batches), block 256. One block handles all 9 taps
// for its 32 pixels, tracks per-(pixel,channel) max in registers, and emits
// g_att = sigmoid(attw . max) directly. No separate attention pass.
__global__ void k_im2col_att(const float* __restrict__ x,
                             const float* __restrict__ attw,
                             const float* __restrict__ attb) {
    __shared__ float stage[32][257];
    __shared__ uint2 spos[KK_][32];
    __shared__ float4 swt[KK_][32];

    int b   = blockIdx.y;
    int hw0 = blockIdx.x * 32;
    int tid = threadIdx.x, lane = tid & 31, w = tid >> 5;

    for (int i = tid; i < KK_ * 32; i += 256) {
        int kk = i >> 5, pp = i & 31;
        spos[kk][pp] = g_pos[(b * KK_ + kk) * HW_ + hw0 + pp];
        swt[kk][pp]  = g_wt [(b * KK_ + kk) * HW_ + hw0 + pp];
    }
    __syncthreads();

    const float* xb0 = x + (size_t)b * C_ * HW_;

    int pl  = tid >> 3;             // pixel this thread owns for the write phase
    int c0  = (tid & 7) * 32;       // channel strip
    int rot = (tid & 7) * 4;        // bank-conflict-free rotation
    int p   = b * HW_ + hw0 + pl;

    float mx[32];
    #pragma unroll
    for (int j = 0; j < 32; ++j) mx[j] = -1e30f;

    for (int kk = 0; kk < KK_; ++kk) {
        uint2 pos = spos[kk][lane];
        float4 wt = swt[kk][lane];
        #pragma unroll 4
        for (int c = w; c < C_; c += 8) {
            const float* xb = xb0 + c * HW_;
            float v = wt.x * xb[pos.x & 0xFFFFu]
                    + wt.y * xb[pos.x >> 16]
                    + wt.z * xb[pos.y & 0xFFFFu]
                    + wt.w * xb[pos.y >> 16];
            stage[lane][c] = v;
        }
        __syncthreads();

        float val[32];
        #pragma unroll
        for (int j = 0; j < 32; ++j) {
            int j2 = (j + rot) & 31;
            val[j2] = stage[pl][c0 + j2];
        }
        union { __nv_bfloat16 bb[32]; uint4 v[4]; } uh, ul;
        #pragma unroll
        for (int j = 0; j < 32; ++j) {
            mx[j] = fmaxf(mx[j], val[j]);
            __nv_bfloat16 h = __float2bfloat16(val[j]);
            uh.bb[j] = h;
            ul.bb[j] = __float2bfloat16(val[j] - __bfloat162float(h));
        }
        size_t base = (size_t)p * KD_ + kk * 256 + c0;
        uint4* dh = (uint4*)(g_bhi + base);
        uint4* dl = (uint4*)(g_blo + base);
        #pragma unroll
        for (int j = 0; j < 4; ++j) { dh[j] = uh.v[j]; dl[j] = ul.v[j]; }
        __syncthreads();
    }

    // attention: dot(attw, mx), reduce across the 8 threads sharing pl
    float acc = 0.0f;
    #pragma unroll
    for (int j = 0; j < 32; ++j) acc += attw[c0 + j] * mx[j];
    #pragma unroll
    for (int s = 4; s; s >>= 1) acc += __shfl_xor_sync(0xFFFFFFFFu, acc, s);
    if ((tid & 7) == 0) g_att[p] = 1.0f / (1.0f + __expf(-(acc + attb[0])));
}

// ================== kernel 3: mma.sync split-bf16 GEMM + att + group-stat epilogue ==================
// CTA 256(M) x 128(N): B read exactly once. K-tile 32, 512 threads (16 warps,
// warp tile 64x32), triple-buffered cp.async, 80B-padded smem rows.
#define ST_A_HI 0
#define ST_A_LO 20480
#define ST_B_HI 40960
#define ST_B_LO 51200
#define STAGE_B 61440
#define GEMM_SMEM (3 * STAGE_B)

__device__ __forceinline__ void load_stage(uint32_t sm, int kt, int p0, int tid) {
    int k0 = kt * 32;
    #pragma unroll
    for (int i = 0; i < 2; ++i) {
        int idx = tid + i * 512;        // 256 rows x 4 chunks
        int r = idx >> 2, q = idx & 3;
        size_t goff = (size_t)r * KD_ + k0 + q * 8;
        cp16(sm + ST_A_HI + r * 80 + q * 16, g_ahi + goff);
        cp16(sm + ST_A_LO + r * 80 + q * 16, g_alo + goff);
    }
    {
        int r = tid >> 2, q = tid & 3;  // 128 rows x 4 chunks
        size_t goff = (size_t)(p0 + r) * KD_ + k0 + q * 8;
        cp16(sm + ST_B_HI + r * 80 + q * 16, g_bhi + goff);
        cp16(sm + ST_B_LO + r * 80 + q * 16, g_blo + goff);
    }
}

__device__ __forceinline__ uint32_t ldsm_addr(uint32_t base, int lane, int row0, int kb0) {
    return base + (uint32_t)(row0 + (lane & 15)) * 80u + (uint32_t)(kb0 + ((lane >> 4) << 4));
}

__global__ __launch_bounds__(512, 1) void k_gemm(float* __restrict__ out) {
    extern __shared__ __align__(128) char smem[];
    uint32_t sbase = smem_to_u32(smem);
    int tid = threadIdx.x, wid = tid >> 5, lane = tid & 31;
    int warpM = wid >> 2, warpN = wid & 3;
    int p0 = blockIdx.x * 128;

    float acc[4][4][4];
    #pragma unroll
    for (int i = 0; i < 4; ++i)
        #pragma unroll
        for (int j = 0; j < 4; ++j)
            #pragma unroll
            for (int q = 0; q < 4; ++q) acc[i][j][q] = 0.0f;

    load_stage(sbase, 0, p0, tid);  CP_COMMIT();
    load_stage(sbase + STAGE_B, 1, p0, tid);  CP_COMMIT();

    for (int kt = 0; kt < 72; ++kt) {
        uint32_t cur = sbase + (uint32_t)(kt % 3) * STAGE_B;
        if (kt + 2 < 72) CP_WAIT(1); else CP_WAIT(0);
        __syncthreads();
        if (kt + 2 < 72) {
            load_stage(sbase + (uint32_t)((kt + 2) % 3) * STAGE_B, kt + 2, p0, tid);
            CP_COMMIT();
        }

        #pragma unroll
        for (int ks = 0; ks < 2; ++ks) {
            uint32_t ah[4][4], al[4][4];
            #pragma unroll
            for (int mt = 0; mt < 4; ++mt) {
                int row = warpM * 64 + mt * 16;
                ldsm_x4(ah[mt], ldsm_addr(cur + ST_A_HI, lane, row, ks * 32));
                ldsm_x4(al[mt], ldsm_addr(cur + ST_A_LO, lane, row, ks * 32));
            }
            #pragma unroll
            for (int ntp = 0; ntp < 2; ++ntp) {
                int nrow = warpN * 32 + ntp * 16;
                uint32_t bh[4], bl[4];
                ldsm_x4(bh, ldsm_addr(cur + ST_B_HI, lane, nrow, ks * 32));
                ldsm_x4(bl, ldsm_addr(cur + ST_B_LO, lane, nrow, ks * 32));
                #pragma unroll
                for (int mt = 0; mt < 4; ++mt) {
                    mma_bf16(acc[mt][ntp * 2],     ah[mt], bh[0], bh[2]);
                    mma_bf16(acc[mt][ntp * 2],     ah[mt], bl[0], bl[2]);
                    mma_bf16(acc[mt][ntp * 2],     al[mt], bh[0], bh[2]);
                    mma_bf16(acc[mt][ntp * 2 + 1], ah[mt], bh[1], bh[3]);
                    mma_bf16(acc[mt][ntp * 2 + 1], ah[mt], bl[1], bl[3]);
                    mma_bf16(acc[mt][ntp * 2 + 1], al[mt], bh[1], bh[3]);
                }
            }
        }
        __syncthreads();
    }

    // epilogue: multiply by att, write out, accumulate GroupNorm partial sums
    int b   = p0 >> 12;
    int hw0 = p0 & 4095;
    int qrow = lane >> 2, qcol = (lane & 3) * 2;

    #pragma unroll
    for (int mt = 0; mt < 4; ++mt) {
        float s0 = 0.0f, s20 = 0.0f, s1 = 0.0f, s21 = 0.0f;
        #pragma unroll
        for (int nt = 0; nt < 4; ++nt) {
            int n = warpN * 32 + nt * 8 + qcol;
            float2 av = *(const float2*)&g_att[p0 + n];
            int o = warpM * 64 + mt * 16 + qrow;
            float* base0 = out + ((size_t)(b * C_ + o)) * HW_ + hw0 + n;
            float* base1 = base0 + 8 * HW_;
            float2 v0, v1;
            v0.x = acc[mt][nt][0] * av.x;  v0.y = acc[mt][nt][1] * av.y;
            v1.x = acc[mt][nt][2] * av.x;  v1.y = acc[mt][nt][3] * av.y;
            *(float2*)base0 = v0;
            *(float2*)base1 = v1;
            s0 += v0.x + v0.y;  s20 += v0.x * v0.x + v0.y * v0.y;
            s1 += v1.x + v1.y;  s21 += v1.x * v1.x + v1.y * v1.y;
        }
        #pragma unroll
        for (int s = 16; s; s >>= 1) {
            s0  += __shfl_xor_sync(0xFFFFFFFFu, s0,  s);
            s20 += __shfl_xor_sync(0xFFFFFFFFu, s20, s);
            s1  += __shfl_xor_sync(0xFFFFFFFFu, s1,  s);
            s21 += __shfl_xor_sync(0xFFFFFFFFu, s21, s);
        }
        if (lane == 0) {
            int g0 = warpM * 8 + mt * 2;
            atomicAdd(&g_gsum [b * 32 + g0],     s0);
            atomicAdd(&g_gsum2[b * 32 + g0],     s20);
            atomicAdd(&g_gsum [b * 32 + g0 + 1], s1);
            atomicAdd(&g_gsum2[b * 32 + g0 + 1], s21);
        }
    }
}

// ================== kernel 4: finalize GroupNorm stats ==================
__global__ void k_finalize() {
    int i = threadIdx.x;   // 128 = B_*G_
    float inv_n = 1.0f / (8.0f * HW_);
    float mean = g_gsum[i] * inv_n;
    float var  = g_gsum2[i] * inv_n - mean * mean;
    g_mean[i] = mean;
    g_istd[i] = rsqrtf(var + EPS_);
}

// ================== kernel 5: normalize + affine + ReLU ==================
__global__ void k_norm(float* __restrict__ out,
                       const float* __restrict__ gamma,
                       const float* __restrict__ beta) {
    int idx = blockIdx.x * 256 + threadIdx.x;
    float v = out[idx];
    int c  = (idx >> 12) & 255;
    int bg = idx >> 15;
    v = (v - g_mean[bg]) * g_istd[bg] * gamma[c] + beta[c];
    out[idx] = fmaxf(v, 0.0f);
}

// ================== launch ==================
extern "C" void kernel_launch(void* const* d_in, const int* in_sizes, int n_in,
                              void* d_out, int out_size) {
    const float* x     = (const float*)d_in[0];
    const float* off   = (const float*)d_in[1];
    const float* wgt   = (const float*)d_in[2];
    const float* attw  = (const float*)d_in[3];
    const float* attb  = (const float*)d_in[4];
    const float* gamma = (const float*)d_in[5];
    const float* beta  = (const float*)d_in[6];
    float* out = (float*)d_out;

    static bool configured = false;
    if (!configured) {
        cudaFuncSetAttribute(k_gemm, cudaFuncAttributeMaxDynamicSharedMemorySize, GEMM_SMEM);
        configured = true;
    }

    k_coords     <<<dim3(16, B_ * KK_), 256>>>(off);
    k_wsplit     <<<(C_ * KD_) / 256, 256>>>(wgt);
    k_im2col_att <<<dim3(HW_ / 32, B_), 256>>>(x, attw, attb);
    k_gemm       <<<NP_ / 128, 512, GEMM_SMEM>>>(out);
    k_finalize   <<<1, B_ * G_>>>();
    k_norm       <<<(B_ * C_ * HW_) / 256, 256>>>(out, gamma, beta);
}

// round 5
// speedup vs baseline: 1.6966x; 1.0094x over previous
#include <cuda_runtime.h>
#include <cuda_bf16.h>
#include <cstdint>

// Problem constants
#define B_   4
#define C_   256
#define H_   64
#define W_   64
#define HW_  4096
#define KK_  9
#define KD_  2304            // C*KK (GEMM K), reordered as k = kk*256 + c
#define NP_  16384           // B*HW (GEMM N)
#define G_   32
#define EPS_ 1e-5f

// ---------------- helpers ----------------
__device__ __forceinline__ uint32_t smem_to_u32(const void* p) {
    uint32_t a;
    asm("{ .reg .u64 t; cvta.to.shared.u64 t, %1; cvt.u32.u64 %0, t; }" : "=r"(a) : "l"(p));
    return a;
}
__device__ __forceinline__ void cp16(uint32_t saddr, const void* g) {
    asm volatile("cp.async.cg.shared.global [%0], [%1], 16;" :: "r"(saddr), "l"(g));
}
#define CP_COMMIT() asm volatile("cp.async.commit_group;" ::: "memory")
#define CP_WAIT(n)  asm volatile("cp.async.wait_group %0;" :: "n"(n) : "memory")

__device__ __forceinline__ void ldsm_x4(uint32_t* r, uint32_t addr) {
    asm volatile("ldmatrix.sync.aligned.m8n8.x4.shared.b16 {%0,%1,%2,%3}, [%4];"
                 : "=r"(r[0]), "=r"(r[1]), "=r"(r[2]), "=r"(r[3]) : "r"(addr));
}
__device__ __forceinline__ void mma_bf16(float* d, const uint32_t* a, uint32_t b0, uint32_t b1) {
    asm volatile(
        "mma.sync.aligned.m16n8k16.row.col.f32.bf16.bf16.f32 "
        "{%0,%1,%2,%3}, {%4,%5,%6,%7}, {%8,%9}, {%0,%1,%2,%3};"
        : "+f"(d[0]), "+f"(d[1]), "+f"(d[2]), "+f"(d[3])
        : "r"(a[0]), "r"(a[1]), "r"(a[2]), "r"(a[3]), "r"(b0), "r"(b1));
}

// -------- scratch (device globals) --------
__device__ uint2          g_pos[B_ * KK_ * HW_];
__device__ float4         g_wt [B_ * KK_ * HW_];
__device__ __nv_bfloat16  g_ahi[C_ * KD_];            // weights hi [o][kk*256+c]
__device__ __nv_bfloat16  g_alo[C_ * KD_];
__device__ __nv_bfloat16  g_bhi[(size_t)NP_ * KD_];   // im2col hi [p][kk*256+c]
__device__ __nv_bfloat16  g_blo[(size_t)NP_ * KD_];
__device__ float          g_att[NP_];
__device__ float          g_gsum [B_ * G_];
__device__ float          g_gsum2[B_ * G_];
__device__ float          g_mean[B_ * G_];
__device__ float          g_istd[B_ * G_];

// ================== kernel 0: sampling coords + weights (+ zero group sums) ==================
__global__ void k_coords(const float* __restrict__ off) {
    int bkk = blockIdx.y;
    int hw  = blockIdx.x * 256 + threadIdx.x;
    int b   = bkk / KK_;
    int kk  = bkk - b * KK_;
    int h   = hw >> 6;
    int w   = hw & 63;

    if (blockIdx.x == 0 && blockIdx.y == 0) {
        int t = threadIdx.x;
        if (t < 128)      g_gsum [t] = 0.0f;
        else              g_gsum2[t - 128] = 0.0f;
    }

    float dy = off[(b * 18 + kk * 2    ) * HW_ + hw];
    float dx = off[(b * 18 + kk * 2 + 1) * HW_ + hw];

    float py = (float)h + (float)(kk / 3 - 1) + dy;
    float px = (float)w + (float)(kk % 3 - 1) + dx;

    float fy = floorf(py), fx = floorf(px);
    int iy0 = (int)fy, ix0 = (int)fx;
    float wy1 = py - fy, wy0 = 1.0f - wy1;
    float wx1 = px - fx, wx0 = 1.0f - wx1;

    bool vy0 = (iy0 >= 0)  && (iy0 < H_);
    bool vy1 = (iy0 >= -1) && (iy0 < H_ - 1);
    bool vx0 = (ix0 >= 0)  && (ix0 < W_);
    bool vx1 = (ix0 >= -1) && (ix0 < W_ - 1);

    float4 wt;
    wt.x = wy0 * wx0 * (float)(vy0 && vx0);
    wt.y = wy0 * wx1 * (float)(vy0 && vx1);
    wt.z = wy1 * wx0 * (float)(vy1 && vx0);
    wt.w = wy1 * wx1 * (float)(vy1 && vx1);

    int y0c = min(max(iy0, 0), H_ - 1);
    int y1c = min(max(iy0 + 1, 0), H_ - 1);
    int x0c = min(max(ix0, 0), W_ - 1);
    int x1c = min(max(ix0 + 1, 0), W_ - 1);

    unsigned p00 = (unsigned)(y0c * W_ + x0c);
    unsigned p01 = (unsigned)(y0c * W_ + x1c);
    unsigned p10 = (unsigned)(y1c * W_ + x0c);
    unsigned p11 = (unsigned)(y1c * W_ + x1c);

    int ci = bkk * HW_ + hw;
    g_pos[ci] = make_uint2(p00 | (p01 << 16), p10 | (p11 << 16));
    g_wt[ci]  = wt;
}

// ================== kernel 1: weight split to bf16 hi/lo, reordered k ==================
// grid (KD_/256, C_): blockIdx.y = output channel o
__global__ void k_wsplit(const float* __restrict__ wgt) {
    int o = blockIdx.y;
    int k = blockIdx.x * 256 + threadIdx.x;   // kk*256 + c
    int kk = k >> 8;
    int c  = k & 255;
    float v = wgt[(o * 256 + c) * 9 + kk];
    __nv_bfloat16 h = __float2bfloat16(v);
    g_ahi[o * KD_ + k] = h;
    g_alo[o * KD_ + k] = __float2bfloat16(v - __bfloat162float(h));
}

// ================== kernel 2: im2col + fused attention ==================
__global__ void k_im2col_att(const float* __restrict__ x,
                             const float* __restrict__ attw,
                             const float* __restrict__ attb) {
    __shared__ float stage[32][257];
    __shared__ uint2 spos[KK_][32];
    __shared__ float4 swt[KK_][32];

    int b   = blockIdx.y;
    int hw0 = blockIdx.x * 32;
    int tid = threadIdx.x, lane = tid & 31, w = tid >> 5;

    for (int i = tid; i < KK_ * 32; i += 256) {
        int kk = i >> 5, pp = i & 31;
        spos[kk][pp] = g_pos[(b * KK_ + kk) * HW_ + hw0 + pp];
        swt[kk][pp]  = g_wt [(b * KK_ + kk) * HW_ + hw0 + pp];
    }
    __syncthreads();

    const float* xb0 = x + (size_t)b * C_ * HW_;

    int pl  = tid >> 3;
    int c0  = (tid & 7) * 32;
    int rot = (tid & 7) * 4;
    int p   = b * HW_ + hw0 + pl;

    float mx[32];
    #pragma unroll
    for (int j = 0; j < 32; ++j) mx[j] = -1e30f;

    for (int kk = 0; kk < KK_; ++kk) {
        uint2 pos = spos[kk][lane];
        float4 wt = swt[kk][lane];
        #pragma unroll 4
        for (int c = w; c < C_; c += 8) {
            const float* xb = xb0 + c * HW_;
            float v = wt.x * xb[pos.x & 0xFFFFu]
                    + wt.y * xb[pos.x >> 16]
                    + wt.z * xb[pos.y & 0xFFFFu]
                    + wt.w * xb[pos.y >> 16];
            stage[lane][c] = v;
        }
        __syncthreads();

        float val[32];
        #pragma unroll
        for (int j = 0; j < 32; ++j) {
            int j2 = (j + rot) & 31;
            val[j2] = stage[pl][c0 + j2];
        }
        union { __nv_bfloat16 bb[32]; uint4 v[4]; } uh, ul;
        #pragma unroll
        for (int j = 0; j < 32; ++j) {
            mx[j] = fmaxf(mx[j], val[j]);
            __nv_bfloat16 h = __float2bfloat16(val[j]);
            uh.bb[j] = h;
            ul.bb[j] = __float2bfloat16(val[j] - __bfloat162float(h));
        }
        size_t base = (size_t)p * KD_ + kk * 256 + c0;
        uint4* dh = (uint4*)(g_bhi + base);
        uint4* dl = (uint4*)(g_blo + base);
        #pragma unroll
        for (int j = 0; j < 4; ++j) { dh[j] = uh.v[j]; dl[j] = ul.v[j]; }
        __syncthreads();
    }

    float acc = 0.0f;
    #pragma unroll
    for (int j = 0; j < 32; ++j) acc += attw[c0 + j] * mx[j];
    #pragma unroll
    for (int s = 4; s; s >>= 1) acc += __shfl_xor_sync(0xFFFFFFFFu, acc, s);
    if ((tid & 7) == 0) g_att[p] = 1.0f / (1.0f + __expf(-(acc + attb[0])));
}

// ================== kernel 3: mma.sync split-bf16 GEMM + att + group-stat epilogue ==================
// CTA 256(M) x 128(N), K-tile 32, 512 threads (16 warps, warp tile 64x32),
// 3-stage cp.async ring, 80B-padded rows, distance-8 accumulator reuse.
#define ST_A_HI 0
#define ST_A_LO 20480
#define ST_B_HI 40960
#define ST_B_LO 51200
#define STAGE_B 61440
#define GEMM_SMEM (3 * STAGE_B)

__global__ __launch_bounds__(512, 1) void k_gemm(float* __restrict__ out) {
    extern __shared__ __align__(128) char smem[];
    uint32_t sbase = smem_to_u32(smem);
    int tid = threadIdx.x, wid = tid >> 5, lane = tid & 31;
    int warpM = wid >> 2, warpN = wid & 3;
    int p0 = blockIdx.x * 128;

    // ---- hoisted cp.async setup: 6 global pointers, advanced by 32 elems/tile ----
    int r = tid >> 2, q = tid & 3;
    const __nv_bfloat16* pAhi0 = g_ahi + (size_t)r * KD_ + q * 8;
    const __nv_bfloat16* pAlo0 = g_alo + (size_t)r * KD_ + q * 8;
    const __nv_bfloat16* pAhi1 = pAhi0 + (size_t)128 * KD_;
    const __nv_bfloat16* pAlo1 = pAlo0 + (size_t)128 * KD_;
    const __nv_bfloat16* pBhi  = g_bhi + (size_t)(p0 + r) * KD_ + q * 8;
    const __nv_bfloat16* pBlo  = g_blo + (size_t)(p0 + r) * KD_ + q * 8;
    uint32_t sA = (uint32_t)(r * 80 + q * 16);            // A hi row r
    uint32_t sB = 40960u + (uint32_t)(r * 80 + q * 16);   // B hi row r

#define LOAD_STAGE(sb) do {                                   \
    cp16((sb) + sA,          pAhi0);                          \
    cp16((sb) + sA + 20480u, pAlo0);                          \
    cp16((sb) + sA + 10240u, pAhi1);                          \
    cp16((sb) + sA + 30720u, pAlo1);                          \
    cp16((sb) + sB,          pBhi);                           \
    cp16((sb) + sB + 10240u, pBlo);                           \
    pAhi0 += 32; pAlo0 += 32; pAhi1 += 32; pAlo1 += 32;       \
    pBhi += 32; pBlo += 32;                                   \
    CP_COMMIT();                                              \
} while (0)

    float acc[4][4][4];
    #pragma unroll
    for (int i = 0; i < 4; ++i)
        #pragma unroll
        for (int j = 0; j < 4; ++j)
            #pragma unroll
            for (int qq = 0; qq < 4; ++qq) acc[i][j][qq] = 0.0f;

    uint32_t laneoff = (uint32_t)((lane & 15) * 80 + ((lane >> 4) << 4));
    uint32_t aoff = (uint32_t)(warpM * 64 * 80) + laneoff;            // A hi frag base
    uint32_t boff = 40960u + (uint32_t)(warpN * 32 * 80) + laneoff;   // B hi frag base

    uint32_t cur = sbase;                      // stage being consumed
    uint32_t nxt = sbase + 2u * STAGE_B;       // stage being filled (kt+2)
    const uint32_t send = sbase + 3u * STAGE_B;

    LOAD_STAGE(sbase);
    LOAD_STAGE(sbase + STAGE_B);

    for (int kt = 0; kt < 72; ++kt) {
        if (kt < 70) { CP_WAIT(1); } else { CP_WAIT(0); }
        __syncthreads();
        if (kt < 70) {
            LOAD_STAGE(nxt);
            nxt += STAGE_B; if (nxt == send) nxt = sbase;
        }

        #pragma unroll
        for (int ks = 0; ks < 2; ++ks) {
            uint32_t ah[4][4], al[4][4];
            #pragma unroll
            for (int mt = 0; mt < 4; ++mt) {
                uint32_t a = cur + aoff + (uint32_t)(mt * 16 * 80 + ks * 32);
                ldsm_x4(ah[mt], a);
                ldsm_x4(al[mt], a + 20480u);
            }
            #pragma unroll
            for (int ntp = 0; ntp < 2; ++ntp) {
                uint32_t badr = cur + boff + (uint32_t)(ntp * 16 * 80 + ks * 32);
                uint32_t bh[4], bl[4];
                ldsm_x4(bh, badr);
                ldsm_x4(bl, badr + 10240u);
                // distance-8 same-accumulator reuse: (combo, mt, half)
                #pragma unroll
                for (int combo = 0; combo < 3; ++combo)
                    #pragma unroll
                    for (int mt = 0; mt < 4; ++mt)
                        #pragma unroll
                        for (int hf = 0; hf < 2; ++hf) {
                            const uint32_t* A = (combo == 2) ? al[mt] : ah[mt];
                            uint32_t b0 = (combo == 1) ? bl[hf]     : bh[hf];
                            uint32_t b1 = (combo == 1) ? bl[hf + 2] : bh[hf + 2];
                            mma_bf16(acc[mt][ntp * 2 + hf], A, b0, b1);
                        }
            }
        }
        cur += STAGE_B; if (cur == send) cur = sbase;
    }

    // epilogue: multiply by att, write out, accumulate GroupNorm partial sums
    int b   = p0 >> 12;
    int hw0 = p0 & 4095;
    int qrow = lane >> 2, qcol = (lane & 3) * 2;

    #pragma unroll
    for (int mt = 0; mt < 4; ++mt) {
        float s0 = 0.0f, s20 = 0.0f, s1 = 0.0f, s21 = 0.0f;
        #pragma unroll
        for (int nt = 0; nt < 4; ++nt) {
            int n = warpN * 32 + nt * 8 + qcol;
            float2 av = *(const float2*)&g_att[p0 + n];
            int o = warpM * 64 + mt * 16 + qrow;
            float* base0 = out + ((size_t)(b * C_ + o)) * HW_ + hw0 + n;
            float* base1 = base0 + 8 * HW_;
            float2 v0, v1;
            v0.x = acc[mt][nt][0] * av.x;  v0.y = acc[mt][nt][1] * av.y;
            v1.x = acc[mt][nt][2] * av.x;  v1.y = acc[mt][nt][3] * av.y;
            *(float2*)base0 = v0;
            *(float2*)base1 = v1;
            s0 += v0.x + v0.y;  s20 += v0.x * v0.x + v0.y * v0.y;
            s1 += v1.x + v1.y;  s21 += v1.x * v1.x + v1.y * v1.y;
        }
        #pragma unroll
        for (int s = 16; s; s >>= 1) {
            s0  += __shfl_xor_sync(0xFFFFFFFFu, s0,  s);
            s20 += __shfl_xor_sync(0xFFFFFFFFu, s20, s);
            s1  += __shfl_xor_sync(0xFFFFFFFFu, s1,  s);
            s21 += __shfl_xor_sync(0xFFFFFFFFu, s21, s);
        }
        if (lane == 0) {
            int g0 = warpM * 8 + mt * 2;
            atomicAdd(&g_gsum [b * 32 + g0],     s0);
            atomicAdd(&g_gsum2[b * 32 + g0],     s20);
            atomicAdd(&g_gsum [b * 32 + g0 + 1], s1);
            atomicAdd(&g_gsum2[b * 32 + g0 + 1], s21);
        }
    }
}

// ================== kernel 4: finalize GroupNorm stats ==================
__global__ void k_finalize() {
    int i = threadIdx.x;   // 128 = B_*G_
    float inv_n = 1.0f / (8.0f * HW_);
    float mean = g_gsum[i] * inv_n;
    float var  = g_gsum2[i] * inv_n - mean * mean;
    g_mean[i] = mean;
    g_istd[i] = rsqrtf(var + EPS_);
}

// ================== kernel 5: normalize + affine + ReLU (float4) ==================
__global__ void k_norm(float* __restrict__ out,
                       const float* __restrict__ gamma,
                       const float* __restrict__ beta) {
    int idx = blockIdx.x * 256 + threadIdx.x;   // element-quad index
    float4 v = ((float4*)out)[idx];
    int e0 = idx << 2;
    int c  = (e0 >> 12) & 255;
    int bg = e0 >> 15;
    float sc = g_istd[bg] * gamma[c];
    float sh = beta[c] - g_mean[bg] * sc;
    v.x = fmaxf(fmaf(v.x, sc, sh), 0.0f);
    v.y = fmaxf(fmaf(v.y, sc, sh), 0.0f);
    v.z = fmaxf(fmaf(v.z, sc, sh), 0.0f);
    v.w = fmaxf(fmaf(v.w, sc, sh), 0.0f);
    ((float4*)out)[idx] = v;
}

// ================== launch ==================
extern "C" void kernel_launch(void* const* d_in, const int* in_sizes, int n_in,
                              void* d_out, int out_size) {
    const float* x     = (const float*)d_in[0];
    const float* off   = (const float*)d_in[1];
    const float* wgt   = (const float*)d_in[2];
    const float* attw  = (const float*)d_in[3];
    const float* attb  = (const float*)d_in[4];
    const float* gamma = (const float*)d_in[5];
    const float* beta  = (const float*)d_in[6];
    float* out = (float*)d_out;

    static bool configured = false;
    if (!configured) {
        cudaFuncSetAttribute(k_gemm, cudaFuncAttributeMaxDynamicSharedMemorySize, GEMM_SMEM);
        configured = true;
    }

    k_coords     <<<dim3(16, B_ * KK_), 256>>>(off);
    k_wsplit     <<<dim3(KD_ / 256, C_), 256>>>(wgt);
    k_im2col_att <<<dim3(HW_ / 32, B_), 256>>>(x, attw, attb);
    k_gemm       <<<NP_ / 128, 512, GEMM_SMEM>>>(out);
    k_finalize   <<<1, B_ * G_>>>();
    k_norm       <<<(B_ * C_ * HW_) / 1024, 256>>>(out, gamma, beta);
}

// round 6
// speedup vs baseline: 2.0138x; 1.1869x over previous
#include <cuda_runtime.h>
#include <cuda_fp16.h>
#include <cstdint>

// Problem constants
#define B_   4
#define C_   256
#define H_   64
#define W_   64
#define HW_  4096
#define KK_  9
#define KD_  2304            // C*KK (GEMM K), reordered as k = kk*256 + c
#define NP_  16384           // B*HW (GEMM N)
#define G_   32
#define EPS_ 1e-5f

// ---------------- helpers ----------------
__device__ __forceinline__ uint32_t smem_to_u32(const void* p) {
    uint32_t a;
    asm("{ .reg .u64 t; cvta.to.shared.u64 t, %1; cvt.u32.u64 %0, t; }" : "=r"(a) : "l"(p));
    return a;
}
__device__ __forceinline__ void cp16(uint32_t saddr, const void* g) {
    asm volatile("cp.async.cg.shared.global [%0], [%1], 16;" :: "r"(saddr), "l"(g));
}
#define CP_COMMIT() asm volatile("cp.async.commit_group;" ::: "memory")
#define CP_WAIT(n)  asm volatile("cp.async.wait_group %0;" :: "n"(n) : "memory")

__device__ __forceinline__ void ldsm_x4(uint32_t* r, uint32_t addr) {
    asm volatile("ldmatrix.sync.aligned.m8n8.x4.shared.b16 {%0,%1,%2,%3}, [%4];"
                 : "=r"(r[0]), "=r"(r[1]), "=r"(r[2]), "=r"(r[3]) : "r"(addr));
}
__device__ __forceinline__ void mma_f16(float* d, const uint32_t* a, uint32_t b0, uint32_t b1) {
    asm volatile(
        "mma.sync.aligned.m16n8k16.row.col.f32.f16.f16.f32 "
        "{%0,%1,%2,%3}, {%4,%5,%6,%7}, {%8,%9}, {%0,%1,%2,%3};"
        : "+f"(d[0]), "+f"(d[1]), "+f"(d[2]), "+f"(d[3])
        : "r"(a[0]), "r"(a[1]), "r"(a[2]), "r"(a[3]), "r"(b0), "r"(b1));
}

// -------- scratch (device globals) --------
__device__ uint2   g_pos[B_ * KK_ * HW_];
__device__ float4  g_wt [B_ * KK_ * HW_];
__device__ __half  g_ahi[C_ * KD_];            // weights hi [o][kk*256+c] fp16
__device__ __half  g_alo[C_ * KD_];            // weights lo
__device__ __half  g_bh [(size_t)NP_ * KD_];   // im2col fp16 [p][kk*256+c] (single)
__device__ float   g_att[NP_];
__device__ float   g_gsum [B_ * G_];
__device__ float   g_gsum2[B_ * G_];
__device__ float   g_mean[B_ * G_];
__device__ float   g_istd[B_ * G_];

// ================== kernel 0: sampling coords + weights (+ zero group sums) ==================
__global__ void k_coords(const float* __restrict__ off) {
    int bkk = blockIdx.y;
    int hw  = blockIdx.x * 256 + threadIdx.x;
    int b   = bkk / KK_;
    int kk  = bkk - b * KK_;
    int h   = hw >> 6;
    int w   = hw & 63;

    if (blockIdx.x == 0 && blockIdx.y == 0) {
        int t = threadIdx.x;
        if (t < 128)      g_gsum [t] = 0.0f;
        else              g_gsum2[t - 128] = 0.0f;
    }

    float dy = off[(b * 18 + kk * 2    ) * HW_ + hw];
    float dx = off[(b * 18 + kk * 2 + 1) * HW_ + hw];

    float py = (float)h + (float)(kk / 3 - 1) + dy;
    float px = (float)w + (float)(kk % 3 - 1) + dx;

    float fy = floorf(py), fx = floorf(px);
    int iy0 = (int)fy, ix0 = (int)fx;
    float wy1 = py - fy, wy0 = 1.0f - wy1;
    float wx1 = px - fx, wx0 = 1.0f - wx1;

    bool vy0 = (iy0 >= 0)  && (iy0 < H_);
    bool vy1 = (iy0 >= -1) && (iy0 < H_ - 1);
    bool vx0 = (ix0 >= 0)  && (ix0 < W_);
    bool vx1 = (ix0 >= -1) && (ix0 < W_ - 1);

    float4 wt;
    wt.x = wy0 * wx0 * (float)(vy0 && vx0);
    wt.y = wy0 * wx1 * (float)(vy0 && vx1);
    wt.z = wy1 * wx0 * (float)(vy1 && vx0);
    wt.w = wy1 * wx1 * (float)(vy1 && vx1);

    int y0c = min(max(iy0, 0), H_ - 1);
    int y1c = min(max(iy0 + 1, 0), H_ - 1);
    int x0c = min(max(ix0, 0), W_ - 1);
    int x1c = min(max(ix0 + 1, 0), W_ - 1);

    unsigned p00 = (unsigned)(y0c * W_ + x0c);
    unsigned p01 = (unsigned)(y0c * W_ + x1c);
    unsigned p10 = (unsigned)(y1c * W_ + x0c);
    unsigned p11 = (unsigned)(y1c * W_ + x1c);

    int ci = bkk * HW_ + hw;
    g_pos[ci] = make_uint2(p00 | (p01 << 16), p10 | (p11 << 16));
    g_wt[ci]  = wt;
}

// ================== kernel 1: weight split to fp16 hi/lo, reordered k ==================
__global__ void k_wsplit(const float* __restrict__ wgt) {
    int o = blockIdx.y;
    int k = blockIdx.x * 256 + threadIdx.x;   // kk*256 + c
    int kk = k >> 8;
    int c  = k & 255;
    float v = wgt[(o * 256 + c) * 9 + kk];
    __half h = __float2half_rn(v);
    g_ahi[o * KD_ + k] = h;
    g_alo[o * KD_ + k] = __float2half_rn(v - __half2float(h));
}

// ================== kernel 2: im2col (fp16 single) + fused attention ==================
__global__ void k_im2col_att(const float* __restrict__ x,
                             const float* __restrict__ attw,
                             const float* __restrict__ attb) {
    __shared__ float stage[32][257];
    __shared__ uint2 spos[KK_][32];
    __shared__ float4 swt[KK_][32];

    int b   = blockIdx.y;
    int hw0 = blockIdx.x * 32;
    int tid = threadIdx.x, lane = tid & 31, w = tid >> 5;

    for (int i = tid; i < KK_ * 32; i += 256) {
        int kk = i >> 5, pp = i & 31;
        spos[kk][pp] = g_pos[(b * KK_ + kk) * HW_ + hw0 + pp];
        swt[kk][pp]  = g_wt [(b * KK_ + kk) * HW_ + hw0 + pp];
    }
    __syncthreads();

    const float* xb0 = x + (size_t)b * C_ * HW_;

    int pl  = tid >> 3;
    int c0  = (tid & 7) * 32;
    int rot = (tid & 7) * 4;
    int p   = b * HW_ + hw0 + pl;

    float mx[32];
    #pragma unroll
    for (int j = 0; j < 32; ++j) mx[j] = -1e30f;

    for (int kk = 0; kk < KK_; ++kk) {
        uint2 pos = spos[kk][lane];
        float4 wt = swt[kk][lane];
        #pragma unroll 4
        for (int c = w; c < C_; c += 8) {
            const float* xb = xb0 + c * HW_;
            float v = wt.x * xb[pos.x & 0xFFFFu]
                    + wt.y * xb[pos.x >> 16]
                    + wt.z * xb[pos.y & 0xFFFFu]
                    + wt.w * xb[pos.y >> 16];
            stage[lane][c] = v;
        }
        __syncthreads();

        float val[32];
        #pragma unroll
        for (int j = 0; j < 32; ++j) {
            int j2 = (j + rot) & 31;
            val[j2] = stage[pl][c0 + j2];
        }
        union { __half hh[32]; uint4 v[4]; } uh;
        #pragma unroll
        for (int j = 0; j < 32; ++j) {
            mx[j] = fmaxf(mx[j], val[j]);
            uh.hh[j] = __float2half_rn(val[j]);
        }
        size_t base = (size_t)p * KD_ + kk * 256 + c0;
        uint4* dh = (uint4*)(g_bh + base);
        #pragma unroll
        for (int j = 0; j < 4; ++j) dh[j] = uh.v[j];
        __syncthreads();
    }

    float acc = 0.0f;
    #pragma unroll
    for (int j = 0; j < 32; ++j) acc += attw[c0 + j] * mx[j];
    #pragma unroll
    for (int s = 4; s; s >>= 1) acc += __shfl_xor_sync(0xFFFFFFFFu, acc, s);
    if ((tid & 7) == 0) g_att[p] = 1.0f / (1.0f + __expf(-(acc + attb[0])));
}

// ================== kernel 3: fp16 2-combo GEMM + att + group-stat epilogue ==================
// CTA 256(M) x 128(N), K-tile 32, 512 threads (16 warps, warp tile 64x32),
// 4-stage cp.async ring, 80B-padded rows.
// Stage layout: Ahi[256x80B]=20480, Alo[256x80B]=20480, B[128x80B]=10240 -> 51200B.
#define STAGE_B 51200
#define GEMM_SMEM (4 * STAGE_B)

__global__ __launch_bounds__(512, 1) void k_gemm(float* __restrict__ out) {
    extern __shared__ __align__(128) char smem[];
    uint32_t sbase = smem_to_u32(smem);
    int tid = threadIdx.x, wid = tid >> 5, lane = tid & 31;
    int warpM = wid >> 2, warpN = wid & 3;
    int p0 = blockIdx.x * 128;

    // ---- hoisted cp.async setup: 5 global pointers, advanced by 32 elems/tile ----
    int r = tid >> 2, q = tid & 3;               // r in 0..127, q chunk
    const __half* pAhi0 = g_ahi + (size_t)r * KD_ + q * 8;
    const __half* pAlo0 = g_alo + (size_t)r * KD_ + q * 8;
    const __half* pAhi1 = pAhi0 + (size_t)128 * KD_;
    const __half* pAlo1 = pAlo0 + (size_t)128 * KD_;
    const __half* pB    = g_bh  + (size_t)(p0 + r) * KD_ + q * 8;
    uint32_t sA = (uint32_t)(r * 80 + q * 16);

#define LOAD_STAGE(sb) do {                                   \
    cp16((sb) + sA,          pAhi0);                          \
    cp16((sb) + sA + 10240u, pAhi1);                          \
    cp16((sb) + sA + 20480u, pAlo0);                          \
    cp16((sb) + sA + 30720u, pAlo1);                          \
    cp16((sb) + sA + 40960u, pB);                             \
    pAhi0 += 32; pAlo0 += 32; pAhi1 += 32; pAlo1 += 32;       \
    pB += 32;                                                 \
    CP_COMMIT();                                              \
} while (0)

    float acc[4][4][4];
    #pragma unroll
    for (int i = 0; i < 4; ++i)
        #pragma unroll
        for (int j = 0; j < 4; ++j)
            #pragma unroll
            for (int qq = 0; qq < 4; ++qq) acc[i][j][qq] = 0.0f;

    uint32_t laneoff = (uint32_t)((lane & 15) * 80 + ((lane >> 4) << 4));
    uint32_t aoff = (uint32_t)(warpM * 64 * 80) + laneoff;            // A hi frag base
    uint32_t boff = 40960u + (uint32_t)(warpN * 32 * 80) + laneoff;   // B frag base

    uint32_t cur = sbase;
    uint32_t nxt = sbase + 3u * STAGE_B;       // stage for kt+3
    const uint32_t send = sbase + 4u * STAGE_B;

    LOAD_STAGE(sbase);
    LOAD_STAGE(sbase + STAGE_B);
    LOAD_STAGE(sbase + 2u * STAGE_B);

    for (int kt = 0; kt < 72; ++kt) {
        if (kt < 69) { CP_WAIT(2); } else { CP_WAIT(0); }
        __syncthreads();
        if (kt < 69) {
            LOAD_STAGE(nxt);
            nxt += STAGE_B; if (nxt == send) nxt = sbase;
        }

        #pragma unroll
        for (int ks = 0; ks < 2; ++ks) {
            uint32_t ah[4][4], al[4][4], bh[2][4];
            #pragma unroll
            for (int mt = 0; mt < 4; ++mt) {
                uint32_t a = cur + aoff + (uint32_t)(mt * 16 * 80 + ks * 32);
                ldsm_x4(ah[mt], a);
                ldsm_x4(al[mt], a + 20480u);
            }
            #pragma unroll
            for (int ntp = 0; ntp < 2; ++ntp)
                ldsm_x4(bh[ntp], cur + boff + (uint32_t)(ntp * 16 * 80 + ks * 32));

            // distance-16 same-accumulator reuse: combo -> mt -> ntp -> hf
            #pragma unroll
            for (int combo = 0; combo < 2; ++combo)
                #pragma unroll
                for (int mt = 0; mt < 4; ++mt)
                    #pragma unroll
                    for (int ntp = 0; ntp < 2; ++ntp)
                        #pragma unroll
                        for (int hf = 0; hf < 2; ++hf) {
                            const uint32_t* A = combo ? al[mt] : ah[mt];
                            mma_f16(acc[mt][ntp * 2 + hf], A, bh[ntp][hf], bh[ntp][hf + 2]);
                        }
        }
        cur += STAGE_B; if (cur == send) cur = sbase;
    }

    // epilogue: multiply by att, write out, accumulate GroupNorm partial sums
    int b   = p0 >> 12;
    int hw0 = p0 & 4095;
    int qrow = lane >> 2, qcol = (lane & 3) * 2;

    #pragma unroll
    for (int mt = 0; mt < 4; ++mt) {
        float s0 = 0.0f, s20 = 0.0f, s1 = 0.0f, s21 = 0.0f;
        #pragma unroll
        for (int nt = 0; nt < 4; ++nt) {
            int n = warpN * 32 + nt * 8 + qcol;
            float2 av = *(const float2*)&g_att[p0 + n];
            int o = warpM * 64 + mt * 16 + qrow;
            float* base0 = out + ((size_t)(b * C_ + o)) * HW_ + hw0 + n;
            float* base1 = base0 + 8 * HW_;
            float2 v0, v1;
            v0.x = acc[mt][nt][0] * av.x;  v0.y = acc[mt][nt][1] * av.y;
            v1.x = acc[mt][nt][2] * av.x;  v1.y = acc[mt][nt][3] * av.y;
            *(float2*)base0 = v0;
            *(float2*)base1 = v1;
            s0 += v0.x + v0.y;  s20 += v0.x * v0.x + v0.y * v0.y;
            s1 += v1.x + v1.y;  s21 += v1.x * v1.x + v1.y * v1.y;
        }
        #pragma unroll
        for (int s = 16; s; s >>= 1) {
            s0  += __shfl_xor_sync(0xFFFFFFFFu, s0,  s);
            s20 += __shfl_xor_sync(0xFFFFFFFFu, s20, s);
            s1  += __shfl_xor_sync(0xFFFFFFFFu, s1,  s);
            s21 += __shfl_xor_sync(0xFFFFFFFFu, s21, s);
        }
        if (lane == 0) {
            int g0 = warpM * 8 + mt * 2;
            atomicAdd(&g_gsum [b * 32 + g0],     s0);
            atomicAdd(&g_gsum2[b * 32 + g0],     s20);
            atomicAdd(&g_gsum [b * 32 + g0 + 1], s1);
            atomicAdd(&g_gsum2[b * 32 + g0 + 1], s21);
        }
    }
}

// ================== kernel 4: finalize GroupNorm stats ==================
__global__ void k_finalize() {
    int i = threadIdx.x;   // 128 = B_*G_
    float inv_n = 1.0f / (8.0f * HW_);
    float mean = g_gsum[i] * inv_n;
    float var  = g_gsum2[i] * inv_n - mean * mean;
    g_mean[i] = mean;
    g_istd[i] = rsqrtf(var + EPS_);
}

// ================== kernel 5: normalize + affine + ReLU (float4) ==================
__global__ void k_norm(float* __restrict__ out,
                       const float* __restrict__ gamma,
                       const float* __restrict__ beta) {
    int idx = blockIdx.x * 256 + threadIdx.x;   // element-quad index
    float4 v = ((float4*)out)[idx];
    int e0 = idx << 2;
    int c  = (e0 >> 12) & 255;
    int bg = e0 >> 15;
    float sc = g_istd[bg] * gamma[c];
    float sh = beta[c] - g_mean[bg] * sc;
    v.x = fmaxf(fmaf(v.x, sc, sh), 0.0f);
    v.y = fmaxf(fmaf(v.y, sc, sh), 0.0f);
    v.z = fmaxf(fmaf(v.z, sc, sh), 0.0f);
    v.w = fmaxf(fmaf(v.w, sc, sh), 0.0f);
    ((float4*)out)[idx] = v;
}

// ================== launch ==================
extern "C" void kernel_launch(void* const* d_in, const int* in_sizes, int n_in,
                              void* d_out, int out_size) {
    const float* x     = (const float*)d_in[0];
    const float* off   = (const float*)d_in[1];
    const float* wgt   = (const float*)d_in[2];
    const float* attw  = (const float*)d_in[3];
    const float* attb  = (const float*)d_in[4];
    const float* gamma = (const float*)d_in[5];
    const float* beta  = (const float*)d_in[6];
    float* out = (float*)d_out;

    static bool configured = false;
    if (!configured) {
        cudaFuncSetAttribute(k_gemm, cudaFuncAttributeMaxDynamicSharedMemorySize, GEMM_SMEM);
        configured = true;
    }

    k_coords     <<<dim3(16, B_ * KK_), 256>>>(off);
    k_wsplit     <<<dim3(KD_ / 256, C_), 256>>>(wgt);
    k_im2col_att <<<dim3(HW_ / 32, B_), 256>>>(x, attw, attb);
    k_gemm       <<<NP_ / 128, 512, GEMM_SMEM>>>(out);
    k_finalize   <<<1, B_ * G_>>>();
    k_norm       <<<(B_ * C_ * HW_) / 1024, 256>>>(out, gamma, beta);
}

// round 7
// speedup vs baseline: 2.8205x; 1.4006x over previous
#include <cuda_runtime.h>
#include <cuda_fp16.h>
#include <cstdint>

// Problem constants
#define B_   4
#define C_   256
#define H_   64
#define W_   64
#define HW_  4096
#define KK_  9
#define KD_  2304            // C*KK (GEMM K), reordered as k = kk*256 + c
#define NP_  16384           // B*HW (GEMM N)
#define G_   32
#define EPS_ 1e-5f

// ---------------- helpers ----------------
__device__ __forceinline__ uint32_t smem_to_u32(const void* p) {
    uint32_t a;
    asm("{ .reg .u64 t; cvta.to.shared.u64 t, %1; cvt.u32.u64 %0, t; }" : "=r"(a) : "l"(p));
    return a;
}
__device__ __forceinline__ void cp16(uint32_t saddr, const void* g) {
    asm volatile("cp.async.cg.shared.global [%0], [%1], 16;" :: "r"(saddr), "l"(g));
}
#define CP_COMMIT() asm volatile("cp.async.commit_group;" ::: "memory")
#define CP_WAIT(n)  asm volatile("cp.async.wait_group %0;" :: "n"(n) : "memory")

__device__ __forceinline__ void ldsm_x4(uint32_t* r, uint32_t addr) {
    asm volatile("ldmatrix.sync.aligned.m8n8.x4.shared.b16 {%0,%1,%2,%3}, [%4];"
                 : "=r"(r[0]), "=r"(r[1]), "=r"(r[2]), "=r"(r[3]) : "r"(addr));
}
__device__ __forceinline__ void mma_f16(float* d, const uint32_t* a, uint32_t b0, uint32_t b1) {
    asm volatile(
        "mma.sync.aligned.m16n8k16.row.col.f32.f16.f16.f32 "
        "{%0,%1,%2,%3}, {%4,%5,%6,%7}, {%8,%9}, {%0,%1,%2,%3};"
        : "+f"(d[0]), "+f"(d[1]), "+f"(d[2]), "+f"(d[3])
        : "r"(a[0]), "r"(a[1]), "r"(a[2]), "r"(a[3]), "r"(b0), "r"(b1));
}

// -------- scratch (device globals) --------
__device__ uint2   g_pos[B_ * KK_ * HW_];
__device__ float4  g_wt [B_ * KK_ * HW_];
__device__ float   g_xt [(size_t)B_ * HW_ * C_];   // x transposed: [b][hw][c], 16MB
__device__ __half  g_ahi[C_ * KD_];                // weights hi [o][kk*256+c]
__device__ __half  g_alo[C_ * KD_];                // weights lo
__device__ __half  g_bh [(size_t)NP_ * KD_];       // im2col fp16 [p][kk*256+c]
__device__ float   g_att[NP_];
__device__ float   g_gsum [B_ * G_];
__device__ float   g_gsum2[B_ * G_];
__device__ float   g_mean[B_ * G_];
__device__ float   g_istd[B_ * G_];

// ================== kernel 0: sampling coords + weights (+ zero group sums) ==================
__global__ void k_coords(const float* __restrict__ off) {
    int bkk = blockIdx.y;
    int hw  = blockIdx.x * 256 + threadIdx.x;
    int b   = bkk / KK_;
    int kk  = bkk - b * KK_;
    int h   = hw >> 6;
    int w   = hw & 63;

    if (blockIdx.x == 0 && blockIdx.y == 0) {
        int t = threadIdx.x;
        if (t < 128)      g_gsum [t] = 0.0f;
        else              g_gsum2[t - 128] = 0.0f;
    }

    float dy = off[(b * 18 + kk * 2    ) * HW_ + hw];
    float dx = off[(b * 18 + kk * 2 + 1) * HW_ + hw];

    float py = (float)h + (float)(kk / 3 - 1) + dy;
    float px = (float)w + (float)(kk % 3 - 1) + dx;

    float fy = floorf(py), fx = floorf(px);
    int iy0 = (int)fy, ix0 = (int)fx;
    float wy1 = py - fy, wy0 = 1.0f - wy1;
    float wx1 = px - fx, wx0 = 1.0f - wx1;

    bool vy0 = (iy0 >= 0)  && (iy0 < H_);
    bool vy1 = (iy0 >= -1) && (iy0 < H_ - 1);
    bool vx0 = (ix0 >= 0)  && (ix0 < W_);
    bool vx1 = (ix0 >= -1) && (ix0 < W_ - 1);

    float4 wt;
    wt.x = wy0 * wx0 * (float)(vy0 && vx0);
    wt.y = wy0 * wx1 * (float)(vy0 && vx1);
    wt.z = wy1 * wx0 * (float)(vy1 && vx0);
    wt.w = wy1 * wx1 * (float)(vy1 && vx1);

    int y0c = min(max(iy0, 0), H_ - 1);
    int y1c = min(max(iy0 + 1, 0), H_ - 1);
    int x0c = min(max(ix0, 0), W_ - 1);
    int x1c = min(max(ix0 + 1, 0), W_ - 1);

    unsigned p00 = (unsigned)(y0c * W_ + x0c);
    unsigned p01 = (unsigned)(y0c * W_ + x1c);
    unsigned p10 = (unsigned)(y1c * W_ + x0c);
    unsigned p11 = (unsigned)(y1c * W_ + x1c);

    int ci = bkk * HW_ + hw;
    g_pos[ci] = make_uint2(p00 | (p01 << 16), p10 | (p11 << 16));
    g_wt[ci]  = wt;
}

// ================== kernel 1: transpose x -> xT[b][hw][c] ==================
// 32x32 tiles, block 32x8
__global__ void k_xpose(const float* __restrict__ x) {
    __shared__ float t[32][33];
    int b   = blockIdx.z;
    int hw0 = blockIdx.x * 32;
    int c0  = blockIdx.y * 32;
    int tx = threadIdx.x, ty = threadIdx.y;

    #pragma unroll
    for (int i = 0; i < 32; i += 8)
        t[ty + i][tx] = x[((size_t)(b * C_ + c0 + ty + i)) * HW_ + hw0 + tx];
    __syncthreads();
    #pragma unroll
    for (int i = 0; i < 32; i += 8)
        g_xt[((size_t)(b * HW_) + hw0 + ty + i) * C_ + c0 + tx] = t[tx][ty + i];
}

// ================== kernel 2: weight split to fp16 hi/lo, reordered k ==================
__global__ void k_wsplit(const float* __restrict__ wgt) {
    int o = blockIdx.y;
    int k = blockIdx.x * 256 + threadIdx.x;   // kk*256 + c
    int kk = k >> 8;
    int c  = k & 255;
    float v = wgt[(o * 256 + c) * 9 + kk];
    __half h = __float2half_rn(v);
    g_ahi[o * KD_ + k] = h;
    g_alo[o * KD_ + k] = __float2half_rn(v - __half2float(h));
}

// ================== kernel 3: im2col from xT (coalesced) + fused attention ==================
// block 256 = 8 warps; warp owns one pixel, loops 9 taps. Grid (HW_/8, B_).
__global__ void k_im2col_att(const float* __restrict__ attw,
                             const float* __restrict__ attb) {
    __shared__ uint2  spos[8][KK_];
    __shared__ float4 swt [8][KK_];

    int b   = blockIdx.y;
    int hw0 = blockIdx.x * 8;
    int tid = threadIdx.x, wid = tid >> 5, lane = tid & 31;

    if (tid < 8 * KK_) {
        int pi = tid / KK_, kk = tid - pi * KK_;
        spos[pi][kk] = g_pos[(b * KK_ + kk) * HW_ + hw0 + pi];
        swt [pi][kk] = g_wt [(b * KK_ + kk) * HW_ + hw0 + pi];
    }
    __syncthreads();

    int p  = b * HW_ + hw0 + wid;
    int c8 = lane * 8;
    const float* xtb = g_xt + (size_t)(b * HW_) * C_ + c8;
    __half* dst0 = g_bh + (size_t)p * KD_ + c8;

    float mx[8];
    #pragma unroll
    for (int j = 0; j < 8; ++j) mx[j] = -1e30f;

    #pragma unroll
    for (int kk = 0; kk < KK_; ++kk) {
        uint2 pos = spos[wid][kk];
        float4 wt = swt[wid][kk];
        const float* r00 = xtb + (size_t)(pos.x & 0xFFFFu) * C_;
        const float* r01 = xtb + (size_t)(pos.x >> 16)     * C_;
        const float* r10 = xtb + (size_t)(pos.y & 0xFFFFu) * C_;
        const float* r11 = xtb + (size_t)(pos.y >> 16)     * C_;

        float4 a0 = *(const float4*)r00,       a1 = *(const float4*)(r00 + 4);
        float4 b0 = *(const float4*)r01,       b1 = *(const float4*)(r01 + 4);
        float4 c0 = *(const float4*)r10,       c1 = *(const float4*)(r10 + 4);
        float4 d0 = *(const float4*)r11,       d1 = *(const float4*)(r11 + 4);

        float val[8];
        val[0] = wt.x * a0.x + wt.y * b0.x + wt.z * c0.x + wt.w * d0.x;
        val[1] = wt.x * a0.y + wt.y * b0.y + wt.z * c0.y + wt.w * d0.y;
        val[2] = wt.x * a0.z + wt.y * b0.z + wt.z * c0.z + wt.w * d0.z;
        val[3] = wt.x * a0.w + wt.y * b0.w + wt.z * c0.w + wt.w * d0.w;
        val[4] = wt.x * a1.x + wt.y * b1.x + wt.z * c1.x + wt.w * d1.x;
        val[5] = wt.x * a1.y + wt.y * b1.y + wt.z * c1.y + wt.w * d1.y;
        val[6] = wt.x * a1.z + wt.y * b1.z + wt.z * c1.z + wt.w * d1.z;
        val[7] = wt.x * a1.w + wt.y * b1.w + wt.z * c1.w + wt.w * d1.w;

        union { __half hh[8]; uint4 v; } u;
        #pragma unroll
        for (int j = 0; j < 8; ++j) {
            mx[j] = fmaxf(mx[j], val[j]);
            u.hh[j] = __float2half_rn(val[j]);
        }
        *(uint4*)(dst0 + kk * 256) = u.v;
    }

    // attention: dot(attw, mx) over this lane's 8 channels, reduce over warp
    float2 w0 = *(const float2*)&attw[c8];
    float2 w1 = *(const float2*)&attw[c8 + 2];
    float2 w2 = *(const float2*)&attw[c8 + 4];
    float2 w3 = *(const float2*)&attw[c8 + 6];
    float acc = w0.x * mx[0] + w0.y * mx[1] + w1.x * mx[2] + w1.y * mx[3]
              + w2.x * mx[4] + w2.y * mx[5] + w3.x * mx[6] + w3.y * mx[7];
    #pragma unroll
    for (int s = 16; s; s >>= 1) acc += __shfl_xor_sync(0xFFFFFFFFu, acc, s);
    if (lane == 0) g_att[p] = 1.0f / (1.0f + __expf(-(acc + attb[0])));
}

// ================== kernel 4: fp16 2-combo GEMM, 2 CTAs/SM ==================
// CTA 128(M) x 128(N), K-tile 32, 256 threads (8 warps, warp tile 64x32),
// 3-stage cp.async ring, 80B-padded rows, 2 CTAs per SM for barrier overlap.
// Stage: Ahi[128x80B]=10240, Alo=10240, B=10240 -> 30720B.
#define STAGE_B 30720
#define GEMM_SMEM (3 * STAGE_B)

__global__ __launch_bounds__(256, 2) void k_gemm(float* __restrict__ out) {
    extern __shared__ __align__(128) char smem[];
    uint32_t sbase = smem_to_u32(smem);
    int tid = threadIdx.x, wid = tid >> 5, lane = tid & 31;
    int warpM = wid >> 2, warpN = wid & 3;
    int p0 = blockIdx.x * 128;
    int m0 = blockIdx.y * 128;

    // ---- loader: thread covers 2 adjacent 16B chunks of one row in each tile ----
    int r = tid >> 1, q = (tid & 1) * 2;         // r 0..127, q in {0,2}
    const __half* pAhi = g_ahi + (size_t)(m0 + r) * KD_ + q * 8;
    const __half* pAlo = g_alo + (size_t)(m0 + r) * KD_ + q * 8;
    const __half* pB   = g_bh  + (size_t)(p0 + r) * KD_ + q * 8;
    uint32_t sA = (uint32_t)(r * 80 + q * 16);

#define LOAD_STAGE(sb) do {                                   \
    cp16((sb) + sA,               pAhi);                      \
    cp16((sb) + sA + 16u,         pAhi + 8);                  \
    cp16((sb) + sA + 10240u,      pAlo);                      \
    cp16((sb) + sA + 10256u,      pAlo + 8);                  \
    cp16((sb) + sA + 20480u,      pB);                        \
    cp16((sb) + sA + 20496u,      pB + 8);                    \
    pAhi += 32; pAlo += 32; pB += 32;                         \
    CP_COMMIT();                                              \
} while (0)

    float acc[4][4][4];
    #pragma unroll
    for (int i = 0; i < 4; ++i)
        #pragma unroll
        for (int j = 0; j < 4; ++j)
            #pragma unroll
            for (int qq = 0; qq < 4; ++qq) acc[i][j][qq] = 0.0f;

    uint32_t laneoff = (uint32_t)((lane & 15) * 80 + ((lane >> 4) << 4));
    uint32_t aoff = (uint32_t)(warpM * 64 * 80) + laneoff;
    uint32_t boff = 20480u + (uint32_t)(warpN * 32 * 80) + laneoff;

    uint32_t cur = sbase;
    uint32_t nxt = sbase + 2u * STAGE_B;
    const uint32_t send = sbase + 3u * STAGE_B;

    LOAD_STAGE(sbase);
    LOAD_STAGE(sbase + STAGE_B);

    for (int kt = 0; kt < 72; ++kt) {
        if (kt < 70) { CP_WAIT(1); } else { CP_WAIT(0); }
        __syncthreads();
        if (kt < 70) {
            LOAD_STAGE(nxt);
            nxt += STAGE_B; if (nxt == send) nxt = sbase;
        }

        #pragma unroll
        for (int ks = 0; ks < 2; ++ks) {
            uint32_t ah[4][4], al[4][4], bh[2][4];
            #pragma unroll
            for (int mt = 0; mt < 4; ++mt) {
                uint32_t a = cur + aoff + (uint32_t)(mt * 16 * 80 + ks * 32);
                ldsm_x4(ah[mt], a);
                ldsm_x4(al[mt], a + 10240u);
            }
            #pragma unroll
            for (int ntp = 0; ntp < 2; ++ntp)
                ldsm_x4(bh[ntp], cur + boff + (uint32_t)(ntp * 16 * 80 + ks * 32));

            #pragma unroll
            for (int combo = 0; combo < 2; ++combo)
                #pragma unroll
                for (int mt = 0; mt < 4; ++mt)
                    #pragma unroll
                    for (int ntp = 0; ntp < 2; ++ntp)
                        #pragma unroll
                        for (int hf = 0; hf < 2; ++hf) {
                            const uint32_t* A = combo ? al[mt] : ah[mt];
                            mma_f16(acc[mt][ntp * 2 + hf], A, bh[ntp][hf], bh[ntp][hf + 2]);
                        }
        }
        cur += STAGE_B; if (cur == send) cur = sbase;
    }

    // epilogue: multiply by att, write out, accumulate GroupNorm partial sums
    int b   = p0 >> 12;
    int hw0 = p0 & 4095;
    int qrow = lane >> 2, qcol = (lane & 3) * 2;

    #pragma unroll
    for (int mt = 0; mt < 4; ++mt) {
        float s0 = 0.0f, s20 = 0.0f, s1 = 0.0f, s21 = 0.0f;
        #pragma unroll
        for (int nt = 0; nt < 4; ++nt) {
            int n = warpN * 32 + nt * 8 + qcol;
            float2 av = *(const float2*)&g_att[p0 + n];
            int o = m0 + warpM * 64 + mt * 16 + qrow;
            float* base0 = out + ((size_t)(b * C_ + o)) * HW_ + hw0 + n;
            float* base1 = base0 + 8 * HW_;
            float2 v0, v1;
            v0.x = acc[mt][nt][0] * av.x;  v0.y = acc[mt][nt][1] * av.y;
            v1.x = acc[mt][nt][2] * av.x;  v1.y = acc[mt][nt][3] * av.y;
            *(float2*)base0 = v0;
            *(float2*)base1 = v1;
            s0 += v0.x + v0.y;  s20 += v0.x * v0.x + v0.y * v0.y;
            s1 += v1.x + v1.y;  s21 += v1.x * v1.x + v1.y * v1.y;
        }
        #pragma unroll
        for (int s = 16; s; s >>= 1) {
            s0  += __shfl_xor_sync(0xFFFFFFFFu, s0,  s);
            s20 += __shfl_xor_sync(0xFFFFFFFFu, s20, s);
            s1  += __shfl_xor_sync(0xFFFFFFFFu, s1,  s);
            s21 += __shfl_xor_sync(0xFFFFFFFFu, s21, s);
        }
        if (lane == 0) {
            int g0 = (m0 >> 3) + warpM * 8 + mt * 2;
            atomicAdd(&g_gsum [b * 32 + g0],     s0);
            atomicAdd(&g_gsum2[b * 32 + g0],     s20);
            atomicAdd(&g_gsum [b * 32 + g0 + 1], s1);
            atomicAdd(&g_gsum2[b * 32 + g0 + 1], s21);
        }
    }
}

// ================== kernel 5: finalize GroupNorm stats ==================
__global__ void k_finalize() {
    int i = threadIdx.x;   // 128 = B_*G_
    float inv_n = 1.0f / (8.0f * HW_);
    float mean = g_gsum[i] * inv_n;
    float var  = g_gsum2[i] * inv_n - mean * mean;
    g_mean[i] = mean;
    g_istd[i] = rsqrtf(var + EPS_);
}

// ================== kernel 6: normalize + affine + ReLU (float4) ==================
__global__ void k_norm(float* __restrict__ out,
                       const float* __restrict__ gamma,
                       const float* __restrict__ beta) {
    int idx = blockIdx.x * 256 + threadIdx.x;   // element-quad index
    float4 v = ((float4*)out)[idx];
    int e0 = idx << 2;
    int c  = (e0 >> 12) & 255;
    int bg = e0 >> 15;
    float sc = g_istd[bg] * gamma[c];
    float sh = beta[c] - g_mean[bg] * sc;
    v.x = fmaxf(fmaf(v.x, sc, sh), 0.0f);
    v.y = fmaxf(fmaf(v.y, sc, sh), 0.0f);
    v.z = fmaxf(fmaf(v.z, sc, sh), 0.0f);
    v.w = fmaxf(fmaf(v.w, sc, sh), 0.0f);
    ((float4*)out)[idx] = v;
}

// ================== launch ==================
extern "C" void kernel_launch(void* const* d_in, const int* in_sizes, int n_in,
                              void* d_out, int out_size) {
    const float* x     = (const float*)d_in[0];
    const float* off   = (const float*)d_in[1];
    const float* wgt   = (const float*)d_in[2];
    const float* attw  = (const float*)d_in[3];
    const float* attb  = (const float*)d_in[4];
    const float* gamma = (const float*)d_in[5];
    const float* beta  = (const float*)d_in[6];
    float* out = (float*)d_out;

    static bool configured = false;
    if (!configured) {
        cudaFuncSetAttribute(k_gemm, cudaFuncAttributeMaxDynamicSharedMemorySize, GEMM_SMEM);
        configured = true;
    }

    k_coords     <<<dim3(16, B_ * KK_), 256>>>(off);
    k_xpose      <<<dim3(HW_ / 32, C_ / 32, B_), dim3(32, 8)>>>(x);
    k_wsplit     <<<dim3(KD_ / 256, C_), 256>>>(wgt);
    k_im2col_att <<<dim3(HW_ / 8, B_), 256>>>(attw, attb);
    k_gemm       <<<dim3(NP_ / 128, 2), 256, GEMM_SMEM>>>(out);
    k_finalize   <<<1, B_ * G_>>>();
    k_norm       <<<(B_ * C_ * HW_) / 1024, 256>>>(out, gamma, beta);
}

// round 8
// speedup vs baseline: 3.4595x; 1.2266x over previous
#include <cuda_runtime.h>
#include <cuda_fp16.h>
#include <cstdint>

// Problem constants
#define B_   4
#define C_   256
#define H_   64
#define W_   64
#define HW_  4096
#define KK_  9
#define KD_  2304            // C*KK (GEMM K), reordered as k = kk*256 + c
#define NP_  16384           // B*HW (GEMM N)
#define G_   32
#define EPS_ 1e-5f

// ---------------- helpers ----------------
__device__ __forceinline__ uint32_t smem_to_u32(const void* p) {
    uint32_t a;
    asm("{ .reg .u64 t; cvta.to.shared.u64 t, %1; cvt.u32.u64 %0, t; }" : "=r"(a) : "l"(p));
    return a;
}
__device__ __forceinline__ void cp16(uint32_t saddr, const void* g) {
    asm volatile("cp.async.cg.shared.global [%0], [%1], 16;" :: "r"(saddr), "l"(g));
}
#define CP_COMMIT() asm volatile("cp.async.commit_group;" ::: "memory")
#define CP_WAIT(n)  asm volatile("cp.async.wait_group %0;" :: "n"(n) : "memory")

__device__ __forceinline__ void ldsm_x4(uint32_t* r, uint32_t addr) {
    asm volatile("ldmatrix.sync.aligned.m8n8.x4.shared.b16 {%0,%1,%2,%3}, [%4];"
                 : "=r"(r[0]), "=r"(r[1]), "=r"(r[2]), "=r"(r[3]) : "r"(addr));
}
__device__ __forceinline__ void mma_f16(float* d, const uint32_t* a, uint32_t b0, uint32_t b1) {
    asm volatile(
        "mma.sync.aligned.m16n8k16.row.col.f32.f16.f16.f32 "
        "{%0,%1,%2,%3}, {%4,%5,%6,%7}, {%8,%9}, {%0,%1,%2,%3};"
        : "+f"(d[0]), "+f"(d[1]), "+f"(d[2]), "+f"(d[3])
        : "r"(a[0]), "r"(a[1]), "r"(a[2]), "r"(a[3]), "r"(b0), "r"(b1));
}

// -------- scratch (device globals) --------
__device__ uint2   g_pos[B_ * KK_ * HW_];
__device__ float4  g_wt [B_ * KK_ * HW_];
__device__ __half  g_xt [(size_t)B_ * HW_ * C_];   // x transposed fp16: [b][hw][c], 8MB
__device__ __half  g_ahi[C_ * KD_];                // weights hi [o][kk*256+c]
__device__ __half  g_alo[C_ * KD_];                // weights lo
__device__ __half  g_bh [(size_t)NP_ * KD_];       // im2col fp16 [p][kk*256+c]
__device__ float   g_att[NP_];
__device__ float   g_gsum [B_ * G_];
__device__ float   g_gsum2[B_ * G_];
__device__ float   g_mean[B_ * G_];
__device__ float   g_istd[B_ * G_];

// ================== kernel 0: sampling coords + weights (+ zero group sums) ==================
__global__ void k_coords(const float* __restrict__ off) {
    int bkk = blockIdx.y;
    int hw  = blockIdx.x * 256 + threadIdx.x;
    int b   = bkk / KK_;
    int kk  = bkk - b * KK_;
    int h   = hw >> 6;
    int w   = hw & 63;

    if (blockIdx.x == 0 && blockIdx.y == 0) {
        int t = threadIdx.x;
        if (t < 128)      g_gsum [t] = 0.0f;
        else              g_gsum2[t - 128] = 0.0f;
    }

    float dy = off[(b * 18 + kk * 2    ) * HW_ + hw];
    float dx = off[(b * 18 + kk * 2 + 1) * HW_ + hw];

    float py = (float)h + (float)(kk / 3 - 1) + dy;
    float px = (float)w + (float)(kk % 3 - 1) + dx;

    float fy = floorf(py), fx = floorf(px);
    int iy0 = (int)fy, ix0 = (int)fx;
    float wy1 = py - fy, wy0 = 1.0f - wy1;
    float wx1 = px - fx, wx0 = 1.0f - wx1;

    bool vy0 = (iy0 >= 0)  && (iy0 < H_);
    bool vy1 = (iy0 >= -1) && (iy0 < H_ - 1);
    bool vx0 = (ix0 >= 0)  && (ix0 < W_);
    bool vx1 = (ix0 >= -1) && (ix0 < W_ - 1);

    float4 wt;
    wt.x = wy0 * wx0 * (float)(vy0 && vx0);
    wt.y = wy0 * wx1 * (float)(vy0 && vx1);
    wt.z = wy1 * wx0 * (float)(vy1 && vx0);
    wt.w = wy1 * wx1 * (float)(vy1 && vx1);

    int y0c = min(max(iy0, 0), H_ - 1);
    int y1c = min(max(iy0 + 1, 0), H_ - 1);
    int x0c = min(max(ix0, 0), W_ - 1);
    int x1c = min(max(ix0 + 1, 0), W_ - 1);

    unsigned p00 = (unsigned)(y0c * W_ + x0c);
    unsigned p01 = (unsigned)(y0c * W_ + x1c);
    unsigned p10 = (unsigned)(y1c * W_ + x0c);
    unsigned p11 = (unsigned)(y1c * W_ + x1c);

    int ci = bkk * HW_ + hw;
    g_pos[ci] = make_uint2(p00 | (p01 << 16), p10 | (p11 << 16));
    g_wt[ci]  = wt;
}

// ================== kernel 1: transpose x -> xT[b][hw][c] (fp16) ==================
__global__ void k_xpose(const float* __restrict__ x) {
    __shared__ float t[32][33];
    int b   = blockIdx.z;
    int hw0 = blockIdx.x * 32;
    int c0  = blockIdx.y * 32;
    int tx = threadIdx.x, ty = threadIdx.y;

    #pragma unroll
    for (int i = 0; i < 32; i += 8)
        t[ty + i][tx] = x[((size_t)(b * C_ + c0 + ty + i)) * HW_ + hw0 + tx];
    __syncthreads();
    #pragma unroll
    for (int i = 0; i < 32; i += 8)
        g_xt[((size_t)(b * HW_) + hw0 + ty + i) * C_ + c0 + tx] = __float2half_rn(t[tx][ty + i]);
}

// ================== kernel 2: weight split to fp16 hi/lo, reordered k ==================
__global__ void k_wsplit(const float* __restrict__ wgt) {
    int o = blockIdx.y;
    int k = blockIdx.x * 256 + threadIdx.x;   // kk*256 + c
    int kk = k >> 8;
    int c  = k & 255;
    float v = wgt[(o * 256 + c) * 9 + kk];
    __half h = __float2half_rn(v);
    g_ahi[o * KD_ + k] = h;
    g_alo[o * KD_ + k] = __float2half_rn(v - __half2float(h));
}

// ================== kernel 3: im2col from fp16 xT + fused attention ==================
// block 256 = 8 warps; warp owns one pixel, loops 9 taps. Grid (HW_/8, B_).
__global__ void k_im2col_att(const float* __restrict__ attw,
                             const float* __restrict__ attb) {
    __shared__ uint2  spos[8][KK_];
    __shared__ float4 swt [8][KK_];

    int b   = blockIdx.y;
    int hw0 = blockIdx.x * 8;
    int tid = threadIdx.x, wid = tid >> 5, lane = tid & 31;

    if (tid < 8 * KK_) {
        int pi = tid / KK_, kk = tid - pi * KK_;
        spos[pi][kk] = g_pos[(b * KK_ + kk) * HW_ + hw0 + pi];
        swt [pi][kk] = g_wt [(b * KK_ + kk) * HW_ + hw0 + pi];
    }
    __syncthreads();

    int p  = b * HW_ + hw0 + wid;
    int c8 = lane * 8;
    const __half* xtb = g_xt + (size_t)(b * HW_) * C_ + c8;
    __half* dst0 = g_bh + (size_t)p * KD_ + c8;

    float mx[8];
    #pragma unroll
    for (int j = 0; j < 8; ++j) mx[j] = -1e30f;

    #pragma unroll
    for (int kk = 0; kk < KK_; ++kk) {
        uint2 pos = spos[wid][kk];
        float4 wt = swt[wid][kk];
        uint4 ua = *(const uint4*)(xtb + (size_t)(pos.x & 0xFFFFu) * C_);
        uint4 ub = *(const uint4*)(xtb + (size_t)(pos.x >> 16)     * C_);
        uint4 uc = *(const uint4*)(xtb + (size_t)(pos.y & 0xFFFFu) * C_);
        uint4 ud = *(const uint4*)(xtb + (size_t)(pos.y >> 16)     * C_);
        const __half2* ha = (const __half2*)&ua;
        const __half2* hb = (const __half2*)&ub;
        const __half2* hc = (const __half2*)&uc;
        const __half2* hd = (const __half2*)&ud;

        float val[8];
        #pragma unroll
        for (int jj = 0; jj < 4; ++jj) {
            float2 fa = __half22float2(ha[jj]);
            float2 fb = __half22float2(hb[jj]);
            float2 fc = __half22float2(hc[jj]);
            float2 fd = __half22float2(hd[jj]);
            val[jj * 2]     = wt.x * fa.x + wt.y * fb.x + wt.z * fc.x + wt.w * fd.x;
            val[jj * 2 + 1] = wt.x * fa.y + wt.y * fb.y + wt.z * fc.y + wt.w * fd.y;
        }

        union { __half hh[8]; uint4 v; } u;
        #pragma unroll
        for (int j = 0; j < 8; ++j) {
            mx[j] = fmaxf(mx[j], val[j]);
            u.hh[j] = __float2half_rn(val[j]);
        }
        *(uint4*)(dst0 + kk * 256) = u.v;
    }

    // attention: dot(attw, mx) over this lane's 8 channels, reduce over warp
    float2 w0 = *(const float2*)&attw[c8];
    float2 w1 = *(const float2*)&attw[c8 + 2];
    float2 w2 = *(const float2*)&attw[c8 + 4];
    float2 w3 = *(const float2*)&attw[c8 + 6];
    float acc = w0.x * mx[0] + w0.y * mx[1] + w1.x * mx[2] + w1.y * mx[3]
              + w2.x * mx[4] + w2.y * mx[5] + w3.x * mx[6] + w3.y * mx[7];
    #pragma unroll
    for (int s = 16; s; s >>= 1) acc += __shfl_xor_sync(0xFFFFFFFFu, acc, s);
    if (lane == 0) g_att[p] = 1.0f / (1.0f + __expf(-(acc + attb[0])));
}

// ================== kernel 4: fp16 2-combo GEMM, warp tile 64x64 ==================
// CTA 128(M) x 128(N), K-tile 32, 128 threads (4 warps, 2x2 grid, warp 64x64),
// 3-stage cp.async ring, 80B-padded rows, 2 CTAs/SM.
// Stage: Ahi[128x80B]=10240, Alo=10240, B=10240 -> 30720B.
#define STAGE_B 30720
#define GEMM_SMEM (3 * STAGE_B)

__global__ __launch_bounds__(128, 2) void k_gemm(float* __restrict__ out) {
    extern __shared__ __align__(128) char smem[];
    uint32_t sbase = smem_to_u32(smem);
    int tid = threadIdx.x, wid = tid >> 5, lane = tid & 31;
    int warpM = wid >> 1, warpN = wid & 1;
    int p0 = blockIdx.x * 128;
    int m0 = blockIdx.y * 128;

    // ---- loader: 128 threads; r = tid>>2 (0..31) row, q = tid&3 chunk; 4 row passes ----
    int r = tid >> 2, q = tid & 3;
    const __half* pAhi = g_ahi + (size_t)(m0 + r) * KD_ + q * 8;
    const __half* pAlo = g_alo + (size_t)(m0 + r) * KD_ + q * 8;
    const __half* pB   = g_bh  + (size_t)(p0 + r) * KD_ + q * 8;
    uint32_t sA = (uint32_t)(r * 80 + q * 16);
    const size_t GSTEP = (size_t)32 * KD_;

#define LOAD_STAGE(sb) do {                                          \
    _Pragma("unroll")                                                \
    for (int i = 0; i < 4; ++i) {                                    \
        uint32_t so = (sb) + sA + (uint32_t)(i * 2560);              \
        cp16(so,          pAhi + i * GSTEP);                         \
        cp16(so + 10240u, pAlo + i * GSTEP);                         \
        cp16(so + 20480u, pB   + i * GSTEP);                         \
    }                                                                \
    pAhi += 32; pAlo += 32; pB += 32;                                \
    CP_COMMIT();                                                     \
} while (0)

    float acc[4][8][4];
    #pragma unroll
    for (int i = 0; i < 4; ++i)
        #pragma unroll
        for (int j = 0; j < 8; ++j)
            #pragma unroll
            for (int qq = 0; qq < 4; ++qq) acc[i][j][qq] = 0.0f;

    uint32_t laneoff = (uint32_t)((lane & 15) * 80 + ((lane >> 4) << 4));
    uint32_t aoff = (uint32_t)(warpM * 64 * 80) + laneoff;
    uint32_t boff = 20480u + (uint32_t)(warpN * 64 * 80) + laneoff;

    uint32_t cur = sbase;
    uint32_t nxt = sbase + 2u * STAGE_B;
    const uint32_t send = sbase + 3u * STAGE_B;

    LOAD_STAGE(sbase);
    LOAD_STAGE(sbase + STAGE_B);

    for (int kt = 0; kt < 72; ++kt) {
        if (kt < 70) { CP_WAIT(1); } else { CP_WAIT(0); }
        __syncthreads();
        if (kt < 70) {
            LOAD_STAGE(nxt);
            nxt += STAGE_B; if (nxt == send) nxt = sbase;
        }

        #pragma unroll
        for (int ks = 0; ks < 2; ++ks) {
            uint32_t ah[4][4], al[4][4], bh[4][4];
            #pragma unroll
            for (int mt = 0; mt < 4; ++mt) {
                uint32_t a = cur + aoff + (uint32_t)(mt * 16 * 80 + ks * 32);
                ldsm_x4(ah[mt], a);
                ldsm_x4(al[mt], a + 10240u);
            }
            #pragma unroll
            for (int ntp = 0; ntp < 4; ++ntp)
                ldsm_x4(bh[ntp], cur + boff + (uint32_t)(ntp * 16 * 80 + ks * 32));

            #pragma unroll
            for (int combo = 0; combo < 2; ++combo)
                #pragma unroll
                for (int mt = 0; mt < 4; ++mt)
                    #pragma unroll
                    for (int ntp = 0; ntp < 4; ++ntp)
                        #pragma unroll
                        for (int hf = 0; hf < 2; ++hf) {
                            const uint32_t* A = combo ? al[mt] : ah[mt];
                            mma_f16(acc[mt][ntp * 2 + hf], A, bh[ntp][hf], bh[ntp][hf + 2]);
                        }
        }
        cur += STAGE_B; if (cur == send) cur = sbase;
    }

    // epilogue: multiply by att, write out, accumulate GroupNorm partial sums
    int b   = p0 >> 12;
    int hw0 = p0 & 4095;
    int qrow = lane >> 2, qcol = (lane & 3) * 2;

    #pragma unroll
    for (int mt = 0; mt < 4; ++mt) {
        float s0 = 0.0f, s20 = 0.0f, s1 = 0.0f, s21 = 0.0f;
        #pragma unroll
        for (int nt = 0; nt < 8; ++nt) {
            int n = warpN * 64 + nt * 8 + qcol;
            float2 av = *(const float2*)&g_att[p0 + n];
            int o = m0 + warpM * 64 + mt * 16 + qrow;
            float* base0 = out + ((size_t)(b * C_ + o)) * HW_ + hw0 + n;
            float* base1 = base0 + 8 * HW_;
            float2 v0, v1;
            v0.x = acc[mt][nt][0] * av.x;  v0.y = acc[mt][nt][1] * av.y;
            v1.x = acc[mt][nt][2] * av.x;  v1.y = acc[mt][nt][3] * av.y;
            *(float2*)base0 = v0;
            *(float2*)base1 = v1;
            s0 += v0.x + v0.y;  s20 += v0.x * v0.x + v0.y * v0.y;
            s1 += v1.x + v1.y;  s21 += v1.x * v1.x + v1.y * v1.y;
        }
        #pragma unroll
        for (int s = 16; s; s >>= 1) {
            s0  += __shfl_xor_sync(0xFFFFFFFFu, s0,  s);
            s20 += __shfl_xor_sync(0xFFFFFFFFu, s20, s);
            s1  += __shfl_xor_sync(0xFFFFFFFFu, s1,  s);
            s21 += __shfl_xor_sync(0xFFFFFFFFu, s21, s);
        }
        if (lane == 0) {
            int g0 = (m0 >> 3) + warpM * 8 + mt * 2;
            atomicAdd(&g_gsum [b * 32 + g0],     s0);
            atomicAdd(&g_gsum2[b * 32 + g0],     s20);
            atomicAdd(&g_gsum [b * 32 + g0 + 1], s1);
            atomicAdd(&g_gsum2[b * 32 + g0 + 1], s21);
        }
    }
}

// ================== kernel 5: finalize GroupNorm stats ==================
__global__ void k_finalize() {
    int i = threadIdx.x;   // 128 = B_*G_
    float inv_n = 1.0f / (8.0f * HW_);
    float mean = g_gsum[i] * inv_n;
    float var  = g_gsum2[i] * inv_n - mean * mean;
    g_mean[i] = mean;
    g_istd[i] = rsqrtf(var + EPS_);
}

// ================== kernel 6: normalize + affine + ReLU (float4) ==================
__global__ void k_norm(float* __restrict__ out,
                       const float* __restrict__ gamma,
                       const float* __restrict__ beta) {
    int idx = blockIdx.x * 256 + threadIdx.x;   // element-quad index
    float4 v = ((float4*)out)[idx];
    int e0 = idx << 2;
    int c  = (e0 >> 12) & 255;
    int bg = e0 >> 15;
    float sc = g_istd[bg] * gamma[c];
    float sh = beta[c] - g_mean[bg] * sc;
    v.x = fmaxf(fmaf(v.x, sc, sh), 0.0f);
    v.y = fmaxf(fmaf(v.y, sc, sh), 0.0f);
    v.z = fmaxf(fmaf(v.z, sc, sh), 0.0f);
    v.w = fmaxf(fmaf(v.w, sc, sh), 0.0f);
    ((float4*)out)[idx] = v;
}

// ================== launch ==================
extern "C" void kernel_launch(void* const* d_in, const int* in_sizes, int n_in,
                              void* d_out, int out_size) {
    const float* x     = (const float*)d_in[0];
    const float* off   = (const float*)d_in[1];
    const float* wgt   = (const float*)d_in[2];
    const float* attw  = (const float*)d_in[3];
    const float* attb  = (const float*)d_in[4];
    const float* gamma = (const float*)d_in[5];
    const float* beta  = (const float*)d_in[6];
    float* out = (float*)d_out;

    static bool configured = false;
    if (!configured) {
        cudaFuncSetAttribute(k_gemm, cudaFuncAttributeMaxDynamicSharedMemorySize, GEMM_SMEM);
        configured = true;
    }

    k_coords     <<<dim3(16, B_ * KK_), 256>>>(off);
    k_xpose      <<<dim3(HW_ / 32, C_ / 32, B_), dim3(32, 8)>>>(x);
    k_wsplit     <<<dim3(KD_ / 256, C_), 256>>>(wgt);
    k_im2col_att <<<dim3(HW_ / 8, B_), 256>>>(attw, attb);
    k_gemm       <<<dim3(NP_ / 128, 2), 128, GEMM_SMEM>>>(out);
    k_finalize   <<<1, B_ * G_>>>();
    k_norm       <<<(B_ * C_ * HW_) / 1024, 256>>>(out, gamma, beta);
}